// round 1
// baseline (speedup 1.0000x reference)
#include <cuda_runtime.h>
#include <math.h>

#define S_LEN 2048
#define E_DIM 768
#define B_SZ  2
#define NH_R  6
#define NH_C  2
#define HD_R  128   // 768/6
#define HD_C  384   // 768/2
#define M_TOT (B_SZ*S_LEN)   // 4096

// -------- scratch (static device globals; no allocation in kernel_launch) ----
__device__ float g_qr[M_TOT*E_DIM];
__device__ float g_kr[M_TOT*E_DIM];
__device__ float g_vr[M_TOT*E_DIM];
__device__ float g_qc[M_TOT*E_DIM];
__device__ float g_kc[M_TOT*E_DIM];
__device__ float g_vc[M_TOT*E_DIM];
__device__ float g_sr[(size_t)B_SZ*NH_R*S_LEN*S_LEN];   // 201 MB
__device__ float g_sc[(size_t)B_SZ*NH_C*S_LEN*S_LEN];   //  67 MB
__device__ float g_ar[M_TOT*E_DIM];
__device__ float g_ac[M_TOT*E_DIM];
__device__ float g_cat[M_TOT*2*E_DIM];

// ============================================================================
// Generic NN GEMM: C = A[M,K] @ B[K,N] (+bias1 +bias2), batched over grid.z.
// Per z: b = z/nh, h = z%nh;  Aoff = z*sA;  Boff = b*sBb + h*sBh;
// Coff = b*sCb + h*sCh.  All dims assumed multiples of (64,64,16).
// ============================================================================
__global__ void __launch_bounds__(256) gemm_nn(
    const float* __restrict__ A, const float* __restrict__ B,
    float* __restrict__ C,
    const float* __restrict__ bias1, const float* __restrict__ bias2,
    int M, int N, int K, int lda, int ldb, int ldc,
    long long sA, long long sBb, long long sBh,
    long long sCb, long long sCh, int nh)
{
    __shared__ float As[16][65];
    __shared__ float Bs[16][65];
    const int tid = threadIdx.x;
    const int tx = tid & 15, ty = tid >> 4;
    const int z = blockIdx.z;
    const int b = z / nh, h = z % nh;
    const float* Ap = A + (long long)z * sA;
    const float* Bp = B + (long long)b * sBb + (long long)h * sBh;
    float* Cp = C + (long long)b * sCb + (long long)h * sCh;
    const int row0 = blockIdx.y * 64, col0 = blockIdx.x * 64;

    float acc[4][4] = {};
    for (int k0 = 0; k0 < K; k0 += 16) {
        #pragma unroll
        for (int p = 0; p < 4; p++) {
            int ar = p * 16 + (tid >> 4);
            int ac = tid & 15;
            As[ac][ar] = Ap[(long long)(row0 + ar) * lda + k0 + ac];
        }
        #pragma unroll
        for (int p = 0; p < 4; p++) {
            int br = p * 4 + (tid >> 6);
            int bc = tid & 63;
            Bs[br][bc] = Bp[(long long)(k0 + br) * ldb + col0 + bc];
        }
        __syncthreads();
        #pragma unroll
        for (int k = 0; k < 16; k++) {
            float av[4], bv[4];
            #pragma unroll
            for (int i = 0; i < 4; i++) av[i] = As[k][ty * 4 + i];
            #pragma unroll
            for (int j = 0; j < 4; j++) bv[j] = Bs[k][tx * 4 + j];
            #pragma unroll
            for (int i = 0; i < 4; i++)
                #pragma unroll
                for (int j = 0; j < 4; j++)
                    acc[i][j] += av[i] * bv[j];
        }
        __syncthreads();
    }
    #pragma unroll
    for (int i = 0; i < 4; i++) {
        int r = row0 + ty * 4 + i;
        #pragma unroll
        for (int j = 0; j < 4; j++) {
            int c = col0 + tx * 4 + j;
            float v = acc[i][j];
            if (bias1) v += bias1[c];
            if (bias2) v += bias2[c];
            Cp[(long long)r * ldc + c] = v;
        }
    }
}

// ============================================================================
// Scores GEMM (NT): Sc[z, t, s] = scale * dot(Q[b,h,t,:], K[b,h,s,:]) + mask.
// Q/K stored as [B*S, E] with head h occupying columns [h*hd, (h+1)*hd).
// mask = am[b,s] (+ cm[b,t,s] if cm != nullptr).
// ============================================================================
__global__ void __launch_bounds__(256) gemm_nt_scores(
    const float* __restrict__ Qb, const float* __restrict__ Kb,
    float* __restrict__ Sc,
    const float* __restrict__ am, const float* __restrict__ cm,
    float scale, int hd, int nh)
{
    __shared__ float As[16][65];
    __shared__ float Bs[16][65];
    const int tid = threadIdx.x;
    const int tx = tid & 15, ty = tid >> 4;
    const int z = blockIdx.z;
    const int b = z / nh, h = z % nh;
    const float* Qp = Qb + (long long)b * S_LEN * E_DIM + h * hd;
    const float* Kp = Kb + (long long)b * S_LEN * E_DIM + h * hd;
    float* Cp = Sc + (long long)z * S_LEN * S_LEN;
    const int row0 = blockIdx.y * 64, col0 = blockIdx.x * 64;

    float acc[4][4] = {};
    for (int k0 = 0; k0 < hd; k0 += 16) {
        #pragma unroll
        for (int p = 0; p < 4; p++) {
            int r = p * 16 + (tid >> 4);
            int c = tid & 15;
            As[c][r] = Qp[(long long)(row0 + r) * E_DIM + k0 + c];
            Bs[c][r] = Kp[(long long)(col0 + r) * E_DIM + k0 + c];
        }
        __syncthreads();
        #pragma unroll
        for (int k = 0; k < 16; k++) {
            float av[4], bv[4];
            #pragma unroll
            for (int i = 0; i < 4; i++) av[i] = As[k][ty * 4 + i];
            #pragma unroll
            for (int j = 0; j < 4; j++) bv[j] = Bs[k][tx * 4 + j];
            #pragma unroll
            for (int i = 0; i < 4; i++)
                #pragma unroll
                for (int j = 0; j < 4; j++)
                    acc[i][j] += av[i] * bv[j];
        }
        __syncthreads();
    }
    #pragma unroll
    for (int i = 0; i < 4; i++) {
        int t = row0 + ty * 4 + i;
        #pragma unroll
        for (int j = 0; j < 4; j++) {
            int s = col0 + tx * 4 + j;
            float m = am[b * S_LEN + s];
            if (cm) m += cm[((long long)b * S_LEN + t) * S_LEN + s];
            Cp[(long long)t * S_LEN + s] = acc[i][j] * scale + m;
        }
    }
}

// ============================================================================
// Row softmax over length-2048 rows. One block (256 thr) per row; values kept
// in registers (8 per thread) -> one global read + one write.
// ============================================================================
__global__ void __launch_bounds__(256) softmax_rows(float* __restrict__ p)
{
    const long long row = blockIdx.x;
    float* r = p + row * S_LEN;
    const int tid = threadIdx.x;
    __shared__ float red[256];

    float v[8];
    float mx = -1e30f;
    #pragma unroll
    for (int i = 0; i < 8; i++) { v[i] = r[tid + i * 256]; mx = fmaxf(mx, v[i]); }
    red[tid] = mx; __syncthreads();
    for (int s = 128; s > 0; s >>= 1) {
        if (tid < s) red[tid] = fmaxf(red[tid], red[tid + s]);
        __syncthreads();
    }
    mx = red[0];
    __syncthreads();

    float sum = 0.f;
    #pragma unroll
    for (int i = 0; i < 8; i++) { v[i] = __expf(v[i] - mx); sum += v[i]; }
    red[tid] = sum; __syncthreads();
    for (int s = 128; s > 0; s >>= 1) {
        if (tid < s) red[tid] += red[tid + s];
        __syncthreads();
    }
    const float inv = 1.0f / red[0];
    #pragma unroll
    for (int i = 0; i < 8; i++) r[tid + i * 256] = v[i] * inv;
}

// ============================================================================
static float* symaddr(const void* s) {
    void* p = nullptr;
    cudaGetSymbolAddress(&p, s);
    return (float*)p;
}

extern "C" void kernel_launch(void* const* d_in, const int* in_sizes, int n_in,
                              void* d_out, int out_size)
{
    const float* x    = (const float*)d_in[0];   // [B,S,E]
    const float* cm   = (const float*)d_in[1];   // [B,S,S]
    const float* am   = (const float*)d_in[2];   // [B,1,1,S]
    const float* rq_w = (const float*)d_in[3];
    const float* rk_w = (const float*)d_in[4];
    const float* rv_w = (const float*)d_in[5];
    const float* ro_w = (const float*)d_in[6];
    const float* cq_w = (const float*)d_in[7];
    const float* ck_w = (const float*)d_in[8];
    const float* cv_w = (const float*)d_in[9];
    const float* co_w = (const float*)d_in[10];
    const float* rq_b = (const float*)d_in[11];
    const float* rk_b = (const float*)d_in[12];
    const float* rv_b = (const float*)d_in[13];
    const float* ro_b = (const float*)d_in[14];
    const float* cq_b = (const float*)d_in[15];
    const float* ck_b = (const float*)d_in[16];
    const float* cv_b = (const float*)d_in[17];
    const float* co_b = (const float*)d_in[18];
    const float* r_cb = (const float*)d_in[19];  // [1,NH_R,1,HD_R] == [E]
    const float* c_cb = (const float*)d_in[20];  // [1,NH_C,1,HD_C] == [E]
    const float* out_w = (const float*)d_in[21]; // [2E, E]
    const float* out_b = (const float*)d_in[22]; // [E]
    float* out = (float*)d_out;

    float* qr = symaddr(g_qr); float* kr = symaddr(g_kr); float* vr = symaddr(g_vr);
    float* qc = symaddr(g_qc); float* kc = symaddr(g_kc); float* vc = symaddr(g_vc);
    float* sr = symaddr(g_sr); float* sc = symaddr(g_sc);
    float* ar = symaddr(g_ar); float* ac = symaddr(g_ac);
    float* cat = symaddr(g_cat);

    dim3 blk(256);

    // ---- Q/K/V projections (cultural bias folded into Q bias) ----
    dim3 gp(E_DIM / 64, M_TOT / 64, 1);
    gemm_nn<<<gp, blk>>>(x, rq_w, qr, rq_b, r_cb, M_TOT, E_DIM, E_DIM,
                         E_DIM, E_DIM, E_DIM, 0, 0, 0, 0, 0, 1);
    gemm_nn<<<gp, blk>>>(x, rk_w, kr, rk_b, nullptr, M_TOT, E_DIM, E_DIM,
                         E_DIM, E_DIM, E_DIM, 0, 0, 0, 0, 0, 1);
    gemm_nn<<<gp, blk>>>(x, rv_w, vr, rv_b, nullptr, M_TOT, E_DIM, E_DIM,
                         E_DIM, E_DIM, E_DIM, 0, 0, 0, 0, 0, 1);
    gemm_nn<<<gp, blk>>>(x, cq_w, qc, cq_b, c_cb, M_TOT, E_DIM, E_DIM,
                         E_DIM, E_DIM, E_DIM, 0, 0, 0, 0, 0, 1);
    gemm_nn<<<gp, blk>>>(x, ck_w, kc, ck_b, nullptr, M_TOT, E_DIM, E_DIM,
                         E_DIM, E_DIM, E_DIM, 0, 0, 0, 0, 0, 1);
    gemm_nn<<<gp, blk>>>(x, cv_w, vc, cv_b, nullptr, M_TOT, E_DIM, E_DIM,
                         E_DIM, E_DIM, E_DIM, 0, 0, 0, 0, 0, 1);

    // ---- scores = Q K^T * scale + mask ----
    const float scale_r = 1.0f / sqrtf((float)HD_R);
    const float scale_c = 1.0f / sqrtf((float)HD_C);
    dim3 gsr(S_LEN / 64, S_LEN / 64, B_SZ * NH_R);
    gemm_nt_scores<<<gsr, blk>>>(qr, kr, sr, am, nullptr, scale_r, HD_R, NH_R);
    dim3 gsc(S_LEN / 64, S_LEN / 64, B_SZ * NH_C);
    gemm_nt_scores<<<gsc, blk>>>(qc, kc, sc, am, cm, scale_c, HD_C, NH_C);

    // ---- softmax ----
    softmax_rows<<<B_SZ * NH_R * S_LEN, 256>>>(sr);
    softmax_rows<<<B_SZ * NH_C * S_LEN, 256>>>(sc);

    // ---- attn = softmax(scores) @ V  (written back in [B,S,E] layout) ----
    dim3 gar(HD_R / 64, S_LEN / 64, B_SZ * NH_R);
    gemm_nn<<<gar, blk>>>(sr, vr, ar, nullptr, nullptr, S_LEN, HD_R, S_LEN,
                          S_LEN, E_DIM, E_DIM,
                          (long long)S_LEN * S_LEN,
                          (long long)S_LEN * E_DIM, HD_R,
                          (long long)S_LEN * E_DIM, HD_R, NH_R);
    dim3 gac(HD_C / 64, S_LEN / 64, B_SZ * NH_C);
    gemm_nn<<<gac, blk>>>(sc, vc, ac, nullptr, nullptr, S_LEN, HD_C, S_LEN,
                          S_LEN, E_DIM, E_DIM,
                          (long long)S_LEN * S_LEN,
                          (long long)S_LEN * E_DIM, HD_C,
                          (long long)S_LEN * E_DIM, HD_C, NH_C);

    // ---- output projections -> concat buffer [M, 2E] ----
    gemm_nn<<<gp, blk>>>(ar, ro_w, cat, ro_b, nullptr, M_TOT, E_DIM, E_DIM,
                         E_DIM, E_DIM, 2 * E_DIM, 0, 0, 0, 0, 0, 1);
    gemm_nn<<<gp, blk>>>(ac, co_w, cat + E_DIM, co_b, nullptr, M_TOT, E_DIM, E_DIM,
                         E_DIM, E_DIM, 2 * E_DIM, 0, 0, 0, 0, 0, 1);

    // ---- final: [M,2E] @ [2E,E] + out_b ----
    gemm_nn<<<gp, blk>>>(cat, out_w, out, out_b, nullptr, M_TOT, E_DIM, 2 * E_DIM,
                         2 * E_DIM, E_DIM, E_DIM, 0, 0, 0, 0, 0, 1);
}

// round 2
// speedup vs baseline: 2.0695x; 2.0695x over previous
#include <cuda_runtime.h>
#include <math.h>
#include <stdint.h>

#define S_LEN 2048
#define E_DIM 768
#define B_SZ  2
#define NH_R  6
#define NH_C  2
#define HD_R  128
#define HD_C  384
#define M_TOT (B_SZ*S_LEN)   // 4096

#define BM 128
#define BN 64
#define BK 32
#define SA  36   // As[m][k] stride
#define SBN 72   // Bs[k][n] stride (NN)
#define SBT 36   // Bs[n][k] stride (NT)

// -------- scratch ------------------------------------------------------------
__device__ float g_qr[M_TOT*E_DIM];
__device__ float g_kr[M_TOT*E_DIM];
__device__ float g_vr[M_TOT*E_DIM];
__device__ float g_qc[M_TOT*E_DIM];
__device__ float g_kc[M_TOT*E_DIM];
__device__ float g_vc[M_TOT*E_DIM];
__device__ float g_sr[(size_t)B_SZ*NH_R*S_LEN*S_LEN];
__device__ float g_sc[(size_t)B_SZ*NH_C*S_LEN*S_LEN];
__device__ float g_ar[M_TOT*E_DIM];
__device__ float g_ac[M_TOT*E_DIM];
__device__ float g_cat[M_TOT*2*E_DIM];

// -------- tf32 helpers -------------------------------------------------------
__device__ __forceinline__ void split_tf32(float x, uint32_t& hi, uint32_t& lo) {
    uint32_t h;
    asm("cvt.rna.tf32.f32 %0, %1;" : "=r"(h) : "f"(x));
    float l = x - __uint_as_float(h);
    uint32_t lw;
    asm("cvt.rna.tf32.f32 %0, %1;" : "=r"(lw) : "f"(l));
    hi = h; lo = lw;
}

__device__ __forceinline__ void mma_tf32(float* c, const uint32_t* a, const uint32_t* b) {
    asm volatile(
        "mma.sync.aligned.m16n8k8.row.col.f32.tf32.tf32.f32 "
        "{%0,%1,%2,%3}, {%4,%5,%6,%7}, {%8,%9}, {%0,%1,%2,%3};"
        : "+f"(c[0]), "+f"(c[1]), "+f"(c[2]), "+f"(c[3])
        : "r"(a[0]), "r"(a[1]), "r"(a[2]), "r"(a[3]), "r"(b[0]), "r"(b[1]));
}

// ============================================================================
// NN GEMM with 3xTF32: C = A[M,K](lda) @ B[K,N](ldb) (+bias1 +bias2).
// Batched over grid.z: b=z/nh, h=z%nh; offsets via strides.
// ============================================================================
__global__ void __launch_bounds__(128) mma_gemm_nn(
    const float* __restrict__ A, const float* __restrict__ B,
    float* __restrict__ C,
    const float* __restrict__ bias1, const float* __restrict__ bias2,
    int K, int lda, int ldb, int ldc,
    long long sA, long long sBb, long long sBh,
    long long sCb, long long sCh, int nh)
{
    __shared__ float As[BM*SA];
    __shared__ float Bs[BK*SBN];
    const int tid = threadIdx.x;
    const int wid = tid >> 5, lane = tid & 31;
    const int gid = lane >> 2, tig = lane & 3;
    const int z = blockIdx.z, b = z / nh, h = z % nh;
    const float* Ap = A + (long long)z * sA;
    const float* Bp = B + (long long)b * sBb + (long long)h * sBh;
    float* Cp = C + (long long)b * sCb + (long long)h * sCh;
    const int row0 = blockIdx.y * BM, col0 = blockIdx.x * BN;

    float acc[2][8][4] = {};

    for (int k0 = 0; k0 < K; k0 += BK) {
        #pragma unroll
        for (int i = 0; i < 8; i++) {
            int lin = i * 128 + tid;
            int m = lin >> 3, k4 = (lin & 7) << 2;
            float4 v = *(const float4*)(Ap + (long long)(row0 + m) * lda + k0 + k4);
            *(float4*)(As + m * SA + k4) = v;
        }
        #pragma unroll
        for (int i = 0; i < 4; i++) {
            int lin = i * 128 + tid;
            int k = lin >> 4, n4 = (lin & 15) << 2;
            float4 v = *(const float4*)(Bp + (long long)(k0 + k) * ldb + col0 + n4);
            *(float4*)(Bs + k * SBN + n4) = v;
        }
        __syncthreads();
        #pragma unroll
        for (int kk = 0; kk < BK; kk += 8) {
            uint32_t ahi[2][4], alo[2][4];
            #pragma unroll
            for (int i = 0; i < 2; i++) {
                int mb = wid * 32 + i * 16 + gid;
                split_tf32(As[mb * SA + kk + tig],           ahi[i][0], alo[i][0]);
                split_tf32(As[(mb + 8) * SA + kk + tig],     ahi[i][1], alo[i][1]);
                split_tf32(As[mb * SA + kk + tig + 4],       ahi[i][2], alo[i][2]);
                split_tf32(As[(mb + 8) * SA + kk + tig + 4], ahi[i][3], alo[i][3]);
            }
            uint32_t bhi[8][2], blo[8][2];
            #pragma unroll
            for (int j = 0; j < 8; j++) {
                split_tf32(Bs[(kk + tig) * SBN + j * 8 + gid],     bhi[j][0], blo[j][0]);
                split_tf32(Bs[(kk + tig + 4) * SBN + j * 8 + gid], bhi[j][1], blo[j][1]);
            }
            #pragma unroll
            for (int i = 0; i < 2; i++)
                #pragma unroll
                for (int j = 0; j < 8; j++) {
                    mma_tf32(acc[i][j], ahi[i], bhi[j]);
                    mma_tf32(acc[i][j], alo[i], bhi[j]);
                    mma_tf32(acc[i][j], ahi[i], blo[j]);
                }
        }
        __syncthreads();
    }

    #pragma unroll
    for (int i = 0; i < 2; i++) {
        int r0 = row0 + wid * 32 + i * 16 + gid;
        #pragma unroll
        for (int j = 0; j < 8; j++) {
            int c = col0 + j * 8 + tig * 2;
            float b0 = 0.f, b1 = 0.f;
            if (bias1) { b0 += bias1[c]; b1 += bias1[c + 1]; }
            if (bias2) { b0 += bias2[c]; b1 += bias2[c + 1]; }
            float2 v0 = { acc[i][j][0] + b0, acc[i][j][1] + b1 };
            float2 v1 = { acc[i][j][2] + b0, acc[i][j][3] + b1 };
            *(float2*)(Cp + (long long)r0 * ldc + c) = v0;
            *(float2*)(Cp + (long long)(r0 + 8) * ldc + c) = v1;
        }
    }
}

// ============================================================================
// Scores NT GEMM with 3xTF32: Sc[z,t,s] = scale*dot(Q[t,:],K[s,:]) + mask.
// ============================================================================
__global__ void __launch_bounds__(128) mma_gemm_nt_scores(
    const float* __restrict__ Qb, const float* __restrict__ Kb,
    float* __restrict__ Sc,
    const float* __restrict__ am, const float* __restrict__ cm,
    float scale, int hd, int nh)
{
    __shared__ float As[BM*SA];
    __shared__ float Bs[BN*SBT];
    const int tid = threadIdx.x;
    const int wid = tid >> 5, lane = tid & 31;
    const int gid = lane >> 2, tig = lane & 3;
    const int z = blockIdx.z, b = z / nh, h = z % nh;
    const float* Qp = Qb + (long long)b * S_LEN * E_DIM + h * hd;
    const float* Kp = Kb + (long long)b * S_LEN * E_DIM + h * hd;
    float* Cp = Sc + (long long)z * S_LEN * S_LEN;
    const int row0 = blockIdx.y * BM, col0 = blockIdx.x * BN;

    float acc[2][8][4] = {};

    for (int k0 = 0; k0 < hd; k0 += BK) {
        #pragma unroll
        for (int i = 0; i < 8; i++) {
            int lin = i * 128 + tid;
            int m = lin >> 3, k4 = (lin & 7) << 2;
            float4 v = *(const float4*)(Qp + (long long)(row0 + m) * E_DIM + k0 + k4);
            *(float4*)(As + m * SA + k4) = v;
        }
        #pragma unroll
        for (int i = 0; i < 4; i++) {
            int lin = i * 128 + tid;
            int n = lin >> 3, k4 = (lin & 7) << 2;
            float4 v = *(const float4*)(Kp + (long long)(col0 + n) * E_DIM + k0 + k4);
            *(float4*)(Bs + n * SBT + k4) = v;
        }
        __syncthreads();
        #pragma unroll
        for (int kk = 0; kk < BK; kk += 8) {
            uint32_t ahi[2][4], alo[2][4];
            #pragma unroll
            for (int i = 0; i < 2; i++) {
                int mb = wid * 32 + i * 16 + gid;
                split_tf32(As[mb * SA + kk + tig],           ahi[i][0], alo[i][0]);
                split_tf32(As[(mb + 8) * SA + kk + tig],     ahi[i][1], alo[i][1]);
                split_tf32(As[mb * SA + kk + tig + 4],       ahi[i][2], alo[i][2]);
                split_tf32(As[(mb + 8) * SA + kk + tig + 4], ahi[i][3], alo[i][3]);
            }
            uint32_t bhi[8][2], blo[8][2];
            #pragma unroll
            for (int j = 0; j < 8; j++) {
                int n = j * 8 + gid;
                split_tf32(Bs[n * SBT + kk + tig],     bhi[j][0], blo[j][0]);
                split_tf32(Bs[n * SBT + kk + tig + 4], bhi[j][1], blo[j][1]);
            }
            #pragma unroll
            for (int i = 0; i < 2; i++)
                #pragma unroll
                for (int j = 0; j < 8; j++) {
                    mma_tf32(acc[i][j], ahi[i], bhi[j]);
                    mma_tf32(acc[i][j], alo[i], bhi[j]);
                    mma_tf32(acc[i][j], ahi[i], blo[j]);
                }
        }
        __syncthreads();
    }

    #pragma unroll
    for (int i = 0; i < 2; i++) {
        int t0 = row0 + wid * 32 + i * 16 + gid;
        #pragma unroll
        for (int j = 0; j < 8; j++) {
            int s = col0 + j * 8 + tig * 2;
            float m0 = am[b * S_LEN + s], m1 = am[b * S_LEN + s + 1];
            float n0 = m0, n1 = m1;
            if (cm) {
                const float* cmr0 = cm + ((long long)b * S_LEN + t0) * S_LEN;
                const float* cmr1 = cmr0 + 8LL * S_LEN;
                m0 += cmr0[s]; m1 += cmr0[s + 1];
                n0 += cmr1[s]; n1 += cmr1[s + 1];
            }
            float2 v0 = { acc[i][j][0] * scale + m0, acc[i][j][1] * scale + m1 };
            float2 v1 = { acc[i][j][2] * scale + n0, acc[i][j][3] * scale + n1 };
            *(float2*)(Cp + (long long)t0 * S_LEN + s) = v0;
            *(float2*)(Cp + (long long)(t0 + 8) * S_LEN + s) = v1;
        }
    }
}

// ============================================================================
__global__ void __launch_bounds__(256) softmax_rows(float* __restrict__ p)
{
    const long long row = blockIdx.x;
    float* r = p + row * S_LEN;
    const int tid = threadIdx.x;
    __shared__ float red[256];

    float v[8];
    float mx = -1e30f;
    #pragma unroll
    for (int i = 0; i < 8; i++) { v[i] = r[tid + i * 256]; mx = fmaxf(mx, v[i]); }
    red[tid] = mx; __syncthreads();
    for (int s = 128; s > 0; s >>= 1) {
        if (tid < s) red[tid] = fmaxf(red[tid], red[tid + s]);
        __syncthreads();
    }
    mx = red[0];
    __syncthreads();

    float sum = 0.f;
    #pragma unroll
    for (int i = 0; i < 8; i++) { v[i] = __expf(v[i] - mx); sum += v[i]; }
    red[tid] = sum; __syncthreads();
    for (int s = 128; s > 0; s >>= 1) {
        if (tid < s) red[tid] += red[tid + s];
        __syncthreads();
    }
    const float inv = 1.0f / red[0];
    #pragma unroll
    for (int i = 0; i < 8; i++) r[tid + i * 256] = v[i] * inv;
}

// ============================================================================
static float* symaddr(const void* s) {
    void* p = nullptr;
    cudaGetSymbolAddress(&p, s);
    return (float*)p;
}

extern "C" void kernel_launch(void* const* d_in, const int* in_sizes, int n_in,
                              void* d_out, int out_size)
{
    const float* x    = (const float*)d_in[0];
    const float* cm   = (const float*)d_in[1];
    const float* am   = (const float*)d_in[2];
    const float* rq_w = (const float*)d_in[3];
    const float* rk_w = (const float*)d_in[4];
    const float* rv_w = (const float*)d_in[5];
    const float* ro_w = (const float*)d_in[6];
    const float* cq_w = (const float*)d_in[7];
    const float* ck_w = (const float*)d_in[8];
    const float* cv_w = (const float*)d_in[9];
    const float* co_w = (const float*)d_in[10];
    const float* rq_b = (const float*)d_in[11];
    const float* rk_b = (const float*)d_in[12];
    const float* rv_b = (const float*)d_in[13];
    const float* ro_b = (const float*)d_in[14];
    const float* cq_b = (const float*)d_in[15];
    const float* ck_b = (const float*)d_in[16];
    const float* cv_b = (const float*)d_in[17];
    const float* co_b = (const float*)d_in[18];
    const float* r_cb = (const float*)d_in[19];
    const float* c_cb = (const float*)d_in[20];
    const float* out_w = (const float*)d_in[21];
    const float* out_b = (const float*)d_in[22];
    float* out = (float*)d_out;

    float* qr = symaddr(g_qr); float* kr = symaddr(g_kr); float* vr = symaddr(g_vr);
    float* qc = symaddr(g_qc); float* kc = symaddr(g_kc); float* vc = symaddr(g_vc);
    float* sr = symaddr(g_sr); float* sc = symaddr(g_sc);
    float* ar = symaddr(g_ar); float* ac = symaddr(g_ac);
    float* cat = symaddr(g_cat);

    dim3 blk(128);

    // ---- Q/K/V projections (cultural bias folded into Q bias) ----
    dim3 gp(E_DIM / BN, M_TOT / BM, 1);
    mma_gemm_nn<<<gp, blk>>>(x, rq_w, qr, rq_b, r_cb, E_DIM, E_DIM, E_DIM, E_DIM,
                             0, 0, 0, 0, 0, 1);
    mma_gemm_nn<<<gp, blk>>>(x, rk_w, kr, rk_b, nullptr, E_DIM, E_DIM, E_DIM, E_DIM,
                             0, 0, 0, 0, 0, 1);
    mma_gemm_nn<<<gp, blk>>>(x, rv_w, vr, rv_b, nullptr, E_DIM, E_DIM, E_DIM, E_DIM,
                             0, 0, 0, 0, 0, 1);
    mma_gemm_nn<<<gp, blk>>>(x, cq_w, qc, cq_b, c_cb, E_DIM, E_DIM, E_DIM, E_DIM,
                             0, 0, 0, 0, 0, 1);
    mma_gemm_nn<<<gp, blk>>>(x, ck_w, kc, ck_b, nullptr, E_DIM, E_DIM, E_DIM, E_DIM,
                             0, 0, 0, 0, 0, 1);
    mma_gemm_nn<<<gp, blk>>>(x, cv_w, vc, cv_b, nullptr, E_DIM, E_DIM, E_DIM, E_DIM,
                             0, 0, 0, 0, 0, 1);

    // ---- scores = Q K^T * scale + mask ----
    const float scale_r = 1.0f / sqrtf((float)HD_R);
    const float scale_c = 1.0f / sqrtf((float)HD_C);
    dim3 gsr(S_LEN / BN, S_LEN / BM, B_SZ * NH_R);
    mma_gemm_nt_scores<<<gsr, blk>>>(qr, kr, sr, am, nullptr, scale_r, HD_R, NH_R);
    dim3 gsc(S_LEN / BN, S_LEN / BM, B_SZ * NH_C);
    mma_gemm_nt_scores<<<gsc, blk>>>(qc, kc, sc, am, cm, scale_c, HD_C, NH_C);

    // ---- softmax ----
    softmax_rows<<<B_SZ * NH_R * S_LEN, 256>>>(sr);
    softmax_rows<<<B_SZ * NH_C * S_LEN, 256>>>(sc);

    // ---- attn = probs @ V ----
    dim3 gar(HD_R / BN, S_LEN / BM, B_SZ * NH_R);
    mma_gemm_nn<<<gar, blk>>>(sr, vr, ar, nullptr, nullptr, S_LEN,
                              S_LEN, E_DIM, E_DIM,
                              (long long)S_LEN * S_LEN,
                              (long long)S_LEN * E_DIM, HD_R,
                              (long long)S_LEN * E_DIM, HD_R, NH_R);
    dim3 gac(HD_C / BN, S_LEN / BM, B_SZ * NH_C);
    mma_gemm_nn<<<gac, blk>>>(sc, vc, ac, nullptr, nullptr, S_LEN,
                              S_LEN, E_DIM, E_DIM,
                              (long long)S_LEN * S_LEN,
                              (long long)S_LEN * E_DIM, HD_C,
                              (long long)S_LEN * E_DIM, HD_C, NH_C);

    // ---- output projections -> concat [M, 2E] ----
    mma_gemm_nn<<<gp, blk>>>(ar, ro_w, cat, ro_b, nullptr, E_DIM,
                             E_DIM, E_DIM, 2 * E_DIM, 0, 0, 0, 0, 0, 1);
    mma_gemm_nn<<<gp, blk>>>(ac, co_w, cat + E_DIM, co_b, nullptr, E_DIM,
                             E_DIM, E_DIM, 2 * E_DIM, 0, 0, 0, 0, 0, 1);

    // ---- final: [M,2E] @ [2E,E] + out_b ----
    mma_gemm_nn<<<gp, blk>>>(cat, out_w, out, out_b, nullptr, 2 * E_DIM,
                             2 * E_DIM, E_DIM, E_DIM, 0, 0, 0, 0, 0, 1);
}

// round 3
// speedup vs baseline: 2.1409x; 1.0345x over previous
#include <cuda_runtime.h>
#include <math.h>
#include <stdint.h>

#define S_LEN 2048
#define E_DIM 768
#define B_SZ  2
#define NH_R  6
#define NH_C  2
#define HD_R  128
#define HD_C  384
#define M_TOT 4096
#define NQKV  4608   // 6 * 768

#define BM 128
#define BN 64
#define BK 32
#define SA  36       // As[m][k] stride (conflict-free frag loads)
#define SBN 72       // Bs[k][n] stride (NN)
#define SBT 36       // Bs[n][k] stride (NT)
#define SMEM_FLOATS (2*BM*SA + 2*2304)
#define SMEM_BYTES  (SMEM_FLOATS*4)   // 55296

// column offsets inside packed QKV output
#define QR_OFF 0
#define KR_OFF 768
#define VR_OFF 1536
#define QC_OFF 2304
#define KC_OFF 3072
#define VC_OFF 3840

// -------- scratch ------------------------------------------------------------
__device__ float g_wqkv[(size_t)E_DIM*NQKV];
__device__ float g_bqkv[NQKV];
__device__ float g_qkv[(size_t)M_TOT*NQKV];
__device__ float g_sr[(size_t)B_SZ*NH_R*S_LEN*S_LEN];
__device__ float g_sc[(size_t)B_SZ*NH_C*S_LEN*S_LEN];
__device__ float g_ar[(size_t)M_TOT*E_DIM];
__device__ float g_ac[(size_t)M_TOT*E_DIM];
__device__ float g_cat[(size_t)M_TOT*2*E_DIM];

// -------- tf32 helpers -------------------------------------------------------
__device__ __forceinline__ void split_tf32(float x, float& hi, float& lo) {
    uint32_t h;
    asm("cvt.rna.tf32.f32 %0, %1;" : "=r"(h) : "f"(x));
    float hf = __uint_as_float(h);
    float l = x - hf;
    uint32_t lw;
    asm("cvt.rna.tf32.f32 %0, %1;" : "=r"(lw) : "f"(l));
    hi = hf; lo = __uint_as_float(lw);
}

__device__ __forceinline__ void split4(float4 v, float4& hi, float4& lo) {
    split_tf32(v.x, hi.x, lo.x);
    split_tf32(v.y, hi.y, lo.y);
    split_tf32(v.z, hi.z, lo.z);
    split_tf32(v.w, hi.w, lo.w);
}

__device__ __forceinline__ void mma_tf32(float* c, const uint32_t* a, const uint32_t* b) {
    asm volatile(
        "mma.sync.aligned.m16n8k8.row.col.f32.tf32.tf32.f32 "
        "{%0,%1,%2,%3}, {%4,%5,%6,%7}, {%8,%9}, {%0,%1,%2,%3};"
        : "+f"(c[0]), "+f"(c[1]), "+f"(c[2]), "+f"(c[3])
        : "r"(a[0]), "r"(a[1]), "r"(a[2]), "r"(a[3]), "r"(b[0]), "r"(b[1]));
}

// ============================================================================
// Pack 6 projection weights [768,768] into W[768, 4608] and biases (cultural
// bias folded into the Q blocks).
// ============================================================================
__global__ void pack_qkv(const float* __restrict__ w0, const float* __restrict__ w1,
                         const float* __restrict__ w2, const float* __restrict__ w3,
                         const float* __restrict__ w4, const float* __restrict__ w5,
                         const float* __restrict__ b0, const float* __restrict__ b1,
                         const float* __restrict__ b2, const float* __restrict__ b3,
                         const float* __restrict__ b4, const float* __restrict__ b5,
                         const float* __restrict__ rcb, const float* __restrict__ ccb,
                         float* __restrict__ W, float* __restrict__ Bv)
{
    const int blk = blockIdx.y;
    const float* w; const float* bb;
    switch (blk) {
        case 0: w = w0; bb = b0; break;
        case 1: w = w1; bb = b1; break;
        case 2: w = w2; bb = b2; break;
        case 3: w = w3; bb = b3; break;
        case 4: w = w4; bb = b4; break;
        default: w = w5; bb = b5; break;
    }
    int idx = blockIdx.x * 256 + threadIdx.x;
    if (idx < E_DIM * E_DIM) {
        int r = idx / E_DIM, c = idx % E_DIM;
        W[(long long)r * NQKV + blk * E_DIM + c] = w[idx];
    }
    if (blockIdx.x == 0) {
        for (int c = threadIdx.x; c < E_DIM; c += 256) {
            float v = bb[c];
            if (blk == 0) v += rcb[c];
            if (blk == 3) v += ccb[c];
            Bv[blk * E_DIM + c] = v;
        }
    }
}

// ============================================================================
// NN GEMM, 3xTF32, pre-split smem planes. C = A[M,K](lda) @ B[K,N](ldb) +bias.
// ============================================================================
__global__ void __launch_bounds__(256, 2) mma_gemm_nn(
    const float* __restrict__ A, const float* __restrict__ B,
    float* __restrict__ C, const float* __restrict__ bias1,
    int K, int lda, int ldb, int ldc,
    long long sA, long long sBb, long long sBh,
    long long sCb, long long sCh, int nh)
{
    extern __shared__ float sm[];
    float* As_hi = sm;
    float* As_lo = As_hi + BM * SA;
    float* Bs_hi = As_lo + BM * SA;
    float* Bs_lo = Bs_hi + BK * SBN;

    const int tid = threadIdx.x;
    const int wid = tid >> 5, lane = tid & 31;
    const int gid = lane >> 2, tig = lane & 3;
    const int wm = wid >> 1, wn = wid & 1;
    const int z = blockIdx.z, b = z / nh, h = z % nh;
    const float* Ap = A + (long long)z * sA;
    const float* Bp = B + (long long)b * sBb + (long long)h * sBh;
    float* Cp = C + (long long)b * sCb + (long long)h * sCh;
    const int row0 = blockIdx.y * BM, col0 = blockIdx.x * BN;

    float4 pa[4], pb[2];
    #pragma unroll
    for (int i = 0; i < 4; i++) {
        int lin = i * 256 + tid; int m = lin >> 3, k4 = (lin & 7) << 2;
        pa[i] = *(const float4*)(Ap + (long long)(row0 + m) * lda + k4);
    }
    #pragma unroll
    for (int i = 0; i < 2; i++) {
        int lin = i * 256 + tid; int k = lin >> 4, n4 = (lin & 15) << 2;
        pb[i] = *(const float4*)(Bp + (long long)k * ldb + col0 + n4);
    }

    float acc[2][4][4] = {};

    for (int k0 = 0; k0 < K; k0 += BK) {
        #pragma unroll
        for (int i = 0; i < 4; i++) {
            int lin = i * 256 + tid; int m = lin >> 3, k4 = (lin & 7) << 2;
            float4 hi, lo; split4(pa[i], hi, lo);
            *(float4*)(As_hi + m * SA + k4) = hi;
            *(float4*)(As_lo + m * SA + k4) = lo;
        }
        #pragma unroll
        for (int i = 0; i < 2; i++) {
            int lin = i * 256 + tid; int k = lin >> 4, n4 = (lin & 15) << 2;
            float4 hi, lo; split4(pb[i], hi, lo);
            *(float4*)(Bs_hi + k * SBN + n4) = hi;
            *(float4*)(Bs_lo + k * SBN + n4) = lo;
        }
        __syncthreads();
        if (k0 + BK < K) {
            #pragma unroll
            for (int i = 0; i < 4; i++) {
                int lin = i * 256 + tid; int m = lin >> 3, k4 = (lin & 7) << 2;
                pa[i] = *(const float4*)(Ap + (long long)(row0 + m) * lda + k0 + BK + k4);
            }
            #pragma unroll
            for (int i = 0; i < 2; i++) {
                int lin = i * 256 + tid; int k = lin >> 4, n4 = (lin & 15) << 2;
                pb[i] = *(const float4*)(Bp + (long long)(k0 + BK + k) * ldb + col0 + n4);
            }
        }
        #pragma unroll
        for (int kk = 0; kk < BK; kk += 8) {
            uint32_t bhi[4][2], blo[4][2];
            #pragma unroll
            for (int j = 0; j < 4; j++) {
                int n = wn * 32 + j * 8 + gid;
                bhi[j][0] = __float_as_uint(Bs_hi[(kk + tig) * SBN + n]);
                bhi[j][1] = __float_as_uint(Bs_hi[(kk + tig + 4) * SBN + n]);
                blo[j][0] = __float_as_uint(Bs_lo[(kk + tig) * SBN + n]);
                blo[j][1] = __float_as_uint(Bs_lo[(kk + tig + 4) * SBN + n]);
            }
            #pragma unroll
            for (int i = 0; i < 2; i++) {
                int mb = wm * 32 + i * 16 + gid;
                uint32_t ahi[4], alo[4];
                ahi[0] = __float_as_uint(As_hi[mb * SA + kk + tig]);
                ahi[1] = __float_as_uint(As_hi[(mb + 8) * SA + kk + tig]);
                ahi[2] = __float_as_uint(As_hi[mb * SA + kk + tig + 4]);
                ahi[3] = __float_as_uint(As_hi[(mb + 8) * SA + kk + tig + 4]);
                alo[0] = __float_as_uint(As_lo[mb * SA + kk + tig]);
                alo[1] = __float_as_uint(As_lo[(mb + 8) * SA + kk + tig]);
                alo[2] = __float_as_uint(As_lo[mb * SA + kk + tig + 4]);
                alo[3] = __float_as_uint(As_lo[(mb + 8) * SA + kk + tig + 4]);
                #pragma unroll
                for (int j = 0; j < 4; j++) {
                    mma_tf32(acc[i][j], ahi, bhi[j]);
                    mma_tf32(acc[i][j], alo, bhi[j]);
                    mma_tf32(acc[i][j], ahi, blo[j]);
                }
            }
        }
        __syncthreads();
    }

    #pragma unroll
    for (int i = 0; i < 2; i++) {
        int r0 = row0 + wm * 32 + i * 16 + gid;
        #pragma unroll
        for (int j = 0; j < 4; j++) {
            int c = col0 + wn * 32 + j * 8 + tig * 2;
            float b0 = 0.f, b1 = 0.f;
            if (bias1) { b0 = bias1[c]; b1 = bias1[c + 1]; }
            float2 v0 = { acc[i][j][0] + b0, acc[i][j][1] + b1 };
            float2 v1 = { acc[i][j][2] + b0, acc[i][j][3] + b1 };
            *(float2*)(Cp + (long long)r0 * ldc + c) = v0;
            *(float2*)(Cp + (long long)(r0 + 8) * ldc + c) = v1;
        }
    }
}

// ============================================================================
// Scores NT GEMM, 3xTF32, pre-split smem. Sc = scale*Q@K^T + masks.
// ============================================================================
__global__ void __launch_bounds__(256, 2) mma_gemm_nt_scores(
    const float* __restrict__ Qb, const float* __restrict__ Kb,
    float* __restrict__ Sc,
    const float* __restrict__ am, const float* __restrict__ cm,
    float scale, int hd, int nh, int ldq)
{
    extern __shared__ float sm[];
    float* As_hi = sm;
    float* As_lo = As_hi + BM * SA;
    float* Bs_hi = As_lo + BM * SA;
    float* Bs_lo = Bs_hi + BN * SBT;

    const int tid = threadIdx.x;
    const int wid = tid >> 5, lane = tid & 31;
    const int gid = lane >> 2, tig = lane & 3;
    const int wm = wid >> 1, wn = wid & 1;
    const int z = blockIdx.z, b = z / nh, h = z % nh;
    const float* Qp = Qb + (long long)b * S_LEN * ldq + h * hd;
    const float* Kp = Kb + (long long)b * S_LEN * ldq + h * hd;
    float* Cp = Sc + (long long)z * S_LEN * S_LEN;
    const int row0 = blockIdx.y * BM, col0 = blockIdx.x * BN;

    float4 pa[4], pb[2];
    #pragma unroll
    for (int i = 0; i < 4; i++) {
        int lin = i * 256 + tid; int m = lin >> 3, k4 = (lin & 7) << 2;
        pa[i] = *(const float4*)(Qp + (long long)(row0 + m) * ldq + k4);
    }
    #pragma unroll
    for (int i = 0; i < 2; i++) {
        int lin = i * 256 + tid; int n = lin >> 3, k4 = (lin & 7) << 2;
        pb[i] = *(const float4*)(Kp + (long long)(col0 + n) * ldq + k4);
    }

    float acc[2][4][4] = {};

    for (int k0 = 0; k0 < hd; k0 += BK) {
        #pragma unroll
        for (int i = 0; i < 4; i++) {
            int lin = i * 256 + tid; int m = lin >> 3, k4 = (lin & 7) << 2;
            float4 hi, lo; split4(pa[i], hi, lo);
            *(float4*)(As_hi + m * SA + k4) = hi;
            *(float4*)(As_lo + m * SA + k4) = lo;
        }
        #pragma unroll
        for (int i = 0; i < 2; i++) {
            int lin = i * 256 + tid; int n = lin >> 3, k4 = (lin & 7) << 2;
            float4 hi, lo; split4(pb[i], hi, lo);
            *(float4*)(Bs_hi + n * SBT + k4) = hi;
            *(float4*)(Bs_lo + n * SBT + k4) = lo;
        }
        __syncthreads();
        if (k0 + BK < hd) {
            #pragma unroll
            for (int i = 0; i < 4; i++) {
                int lin = i * 256 + tid; int m = lin >> 3, k4 = (lin & 7) << 2;
                pa[i] = *(const float4*)(Qp + (long long)(row0 + m) * ldq + k0 + BK + k4);
            }
            #pragma unroll
            for (int i = 0; i < 2; i++) {
                int lin = i * 256 + tid; int n = lin >> 3, k4 = (lin & 7) << 2;
                pb[i] = *(const float4*)(Kp + (long long)(col0 + n) * ldq + k0 + BK + k4);
            }
        }
        #pragma unroll
        for (int kk = 0; kk < BK; kk += 8) {
            uint32_t bhi[4][2], blo[4][2];
            #pragma unroll
            for (int j = 0; j < 4; j++) {
                int n = wn * 32 + j * 8 + gid;
                bhi[j][0] = __float_as_uint(Bs_hi[n * SBT + kk + tig]);
                bhi[j][1] = __float_as_uint(Bs_hi[n * SBT + kk + tig + 4]);
                blo[j][0] = __float_as_uint(Bs_lo[n * SBT + kk + tig]);
                blo[j][1] = __float_as_uint(Bs_lo[n * SBT + kk + tig + 4]);
            }
            #pragma unroll
            for (int i = 0; i < 2; i++) {
                int mb = wm * 32 + i * 16 + gid;
                uint32_t ahi[4], alo[4];
                ahi[0] = __float_as_uint(As_hi[mb * SA + kk + tig]);
                ahi[1] = __float_as_uint(As_hi[(mb + 8) * SA + kk + tig]);
                ahi[2] = __float_as_uint(As_hi[mb * SA + kk + tig + 4]);
                ahi[3] = __float_as_uint(As_hi[(mb + 8) * SA + kk + tig + 4]);
                alo[0] = __float_as_uint(As_lo[mb * SA + kk + tig]);
                alo[1] = __float_as_uint(As_lo[(mb + 8) * SA + kk + tig]);
                alo[2] = __float_as_uint(As_lo[mb * SA + kk + tig + 4]);
                alo[3] = __float_as_uint(As_lo[(mb + 8) * SA + kk + tig + 4]);
                #pragma unroll
                for (int j = 0; j < 4; j++) {
                    mma_tf32(acc[i][j], ahi, bhi[j]);
                    mma_tf32(acc[i][j], alo, bhi[j]);
                    mma_tf32(acc[i][j], ahi, blo[j]);
                }
            }
        }
        __syncthreads();
    }

    #pragma unroll
    for (int i = 0; i < 2; i++) {
        int t0 = row0 + wm * 32 + i * 16 + gid;
        #pragma unroll
        for (int j = 0; j < 4; j++) {
            int s = col0 + wn * 32 + j * 8 + tig * 2;
            float m0 = am[b * S_LEN + s], m1 = am[b * S_LEN + s + 1];
            float n0 = m0, n1 = m1;
            if (cm) {
                const float* cmr0 = cm + ((long long)b * S_LEN + t0) * S_LEN;
                const float* cmr1 = cmr0 + 8LL * S_LEN;
                m0 += cmr0[s]; m1 += cmr0[s + 1];
                n0 += cmr1[s]; n1 += cmr1[s + 1];
            }
            float2 v0 = { acc[i][j][0] * scale + m0, acc[i][j][1] * scale + m1 };
            float2 v1 = { acc[i][j][2] * scale + n0, acc[i][j][3] * scale + n1 };
            *(float2*)(Cp + (long long)t0 * S_LEN + s) = v0;
            *(float2*)(Cp + (long long)(t0 + 8) * S_LEN + s) = v1;
        }
    }
}

// ============================================================================
__global__ void __launch_bounds__(256) softmax_rows(float* __restrict__ p)
{
    const long long row = blockIdx.x;
    float* r = p + row * S_LEN;
    const int tid = threadIdx.x;
    __shared__ float red[256];

    float v[8];
    float mx = -1e30f;
    #pragma unroll
    for (int i = 0; i < 8; i++) { v[i] = r[tid + i * 256]; mx = fmaxf(mx, v[i]); }
    red[tid] = mx; __syncthreads();
    for (int s = 128; s > 0; s >>= 1) {
        if (tid < s) red[tid] = fmaxf(red[tid], red[tid + s]);
        __syncthreads();
    }
    mx = red[0];
    __syncthreads();

    float sum = 0.f;
    #pragma unroll
    for (int i = 0; i < 8; i++) { v[i] = __expf(v[i] - mx); sum += v[i]; }
    red[tid] = sum; __syncthreads();
    for (int s = 128; s > 0; s >>= 1) {
        if (tid < s) red[tid] += red[tid + s];
        __syncthreads();
    }
    const float inv = 1.0f / red[0];
    #pragma unroll
    for (int i = 0; i < 8; i++) r[tid + i * 256] = v[i] * inv;
}

// ============================================================================
static float* symaddr(const void* s) {
    void* p = nullptr;
    cudaGetSymbolAddress(&p, s);
    return (float*)p;
}

extern "C" void kernel_launch(void* const* d_in, const int* in_sizes, int n_in,
                              void* d_out, int out_size)
{
    const float* x    = (const float*)d_in[0];
    const float* cm   = (const float*)d_in[1];
    const float* am   = (const float*)d_in[2];
    const float* rq_w = (const float*)d_in[3];
    const float* rk_w = (const float*)d_in[4];
    const float* rv_w = (const float*)d_in[5];
    const float* ro_w = (const float*)d_in[6];
    const float* cq_w = (const float*)d_in[7];
    const float* ck_w = (const float*)d_in[8];
    const float* cv_w = (const float*)d_in[9];
    const float* co_w = (const float*)d_in[10];
    const float* rq_b = (const float*)d_in[11];
    const float* rk_b = (const float*)d_in[12];
    const float* rv_b = (const float*)d_in[13];
    const float* ro_b = (const float*)d_in[14];
    const float* cq_b = (const float*)d_in[15];
    const float* ck_b = (const float*)d_in[16];
    const float* cv_b = (const float*)d_in[17];
    const float* co_b = (const float*)d_in[18];
    const float* r_cb = (const float*)d_in[19];
    const float* c_cb = (const float*)d_in[20];
    const float* out_w = (const float*)d_in[21];
    const float* out_b = (const float*)d_in[22];
    float* out = (float*)d_out;

    float* wqkv = symaddr(g_wqkv); float* bqkv = symaddr(g_bqkv);
    float* qkv = symaddr(g_qkv);
    float* sr = symaddr(g_sr); float* sc = symaddr(g_sc);
    float* ar = symaddr(g_ar); float* ac = symaddr(g_ac);
    float* cat = symaddr(g_cat);

    static bool attr_done = false;
    cudaFuncSetAttribute(mma_gemm_nn, cudaFuncAttributeMaxDynamicSharedMemorySize, SMEM_BYTES);
    cudaFuncSetAttribute(mma_gemm_nt_scores, cudaFuncAttributeMaxDynamicSharedMemorySize, SMEM_BYTES);
    (void)attr_done;

    dim3 blk(256);

    // ---- pack weights/biases ----
    dim3 gpk((E_DIM * E_DIM + 255) / 256, 6);
    pack_qkv<<<gpk, blk>>>(rq_w, rk_w, rv_w, cq_w, ck_w, cv_w,
                           rq_b, rk_b, rv_b, cq_b, ck_b, cv_b,
                           r_cb, c_cb, wqkv, bqkv);

    // ---- fused QKV projection: [4096,768] @ [768,4608] ----
    dim3 gq(NQKV / BN, M_TOT / BM, 1);
    mma_gemm_nn<<<gq, blk, SMEM_BYTES>>>(x, wqkv, qkv, bqkv,
                                         E_DIM, E_DIM, NQKV, NQKV,
                                         0, 0, 0, 0, 0, 1);

    // ---- scores ----
    const float scale_r = 1.0f / sqrtf((float)HD_R);
    const float scale_c = 1.0f / sqrtf((float)HD_C);
    dim3 gsr(S_LEN / BN, S_LEN / BM, B_SZ * NH_R);
    mma_gemm_nt_scores<<<gsr, blk, SMEM_BYTES>>>(qkv + QR_OFF, qkv + KR_OFF, sr,
                                                 am, nullptr, scale_r, HD_R, NH_R, NQKV);
    dim3 gsc(S_LEN / BN, S_LEN / BM, B_SZ * NH_C);
    mma_gemm_nt_scores<<<gsc, blk, SMEM_BYTES>>>(qkv + QC_OFF, qkv + KC_OFF, sc,
                                                 am, cm, scale_c, HD_C, NH_C, NQKV);

    // ---- softmax ----
    softmax_rows<<<B_SZ * NH_R * S_LEN, 256>>>(sr);
    softmax_rows<<<B_SZ * NH_C * S_LEN, 256>>>(sc);

    // ---- attn = probs @ V ----
    dim3 gar(HD_R / BN, S_LEN / BM, B_SZ * NH_R);
    mma_gemm_nn<<<gar, blk, SMEM_BYTES>>>(sr, qkv + VR_OFF, ar, nullptr,
                                          S_LEN, S_LEN, NQKV, E_DIM,
                                          (long long)S_LEN * S_LEN,
                                          (long long)S_LEN * NQKV, HD_R,
                                          (long long)S_LEN * E_DIM, HD_R, NH_R);
    dim3 gac(HD_C / BN, S_LEN / BM, B_SZ * NH_C);
    mma_gemm_nn<<<gac, blk, SMEM_BYTES>>>(sc, qkv + VC_OFF, ac, nullptr,
                                          S_LEN, S_LEN, NQKV, E_DIM,
                                          (long long)S_LEN * S_LEN,
                                          (long long)S_LEN * NQKV, HD_C,
                                          (long long)S_LEN * E_DIM, HD_C, NH_C);

    // ---- output projections -> concat [M, 2E] ----
    dim3 gp(E_DIM / BN, M_TOT / BM, 1);
    mma_gemm_nn<<<gp, blk, SMEM_BYTES>>>(ar, ro_w, cat, ro_b,
                                         E_DIM, E_DIM, E_DIM, 2 * E_DIM,
                                         0, 0, 0, 0, 0, 1);
    mma_gemm_nn<<<gp, blk, SMEM_BYTES>>>(ac, co_w, cat + E_DIM, co_b,
                                         E_DIM, E_DIM, E_DIM, 2 * E_DIM,
                                         0, 0, 0, 0, 0, 1);

    // ---- final: [M,2E] @ [2E,E] + out_b ----
    mma_gemm_nn<<<gp, blk, SMEM_BYTES>>>(cat, out_w, out, out_b,
                                         2 * E_DIM, 2 * E_DIM, E_DIM, E_DIM,
                                         0, 0, 0, 0, 0, 1);
}

// round 4
// speedup vs baseline: 3.0347x; 1.4175x over previous
#include <cuda_runtime.h>
#include <cuda_bf16.h>
#include <math.h>
#include <stdint.h>

#define S_LEN 2048
#define E_DIM 768
#define B_SZ  2
#define NH_R  6
#define NH_C  2
#define HD_R  128
#define HD_C  384
#define M_TOT 4096
#define NQKV  4608

// smem strides (uint2 units); stride mod 16 == 4 -> conflict-free LDS.64 frags
#define SP_A  20
#define SP_BN 68
#define SP_BT 20

// -------- scratch ------------------------------------------------------------
__device__ uint2 g_xp[(size_t)M_TOT*384];            // x packed F1
__device__ uint2 g_wqkvp[(size_t)384*NQKV];          // qkv weights F2
__device__ float g_bqkv[NQKV];
__device__ float g_qkv[(size_t)M_TOT*NQKV];          // fp32 qkv (for V split)
__device__ uint2 g_qkvp[(size_t)M_TOT*2304];         // qkv packed F1 (Q,K use)
__device__ uint2 g_vf2[(size_t)B_SZ*1024*1536];      // V packed F2
__device__ float g_sr[(size_t)B_SZ*NH_R*S_LEN*S_LEN];
__device__ float g_sc[(size_t)B_SZ*NH_C*S_LEN*S_LEN];
__device__ uint2 g_srp[(size_t)B_SZ*NH_R*S_LEN*1024];
__device__ uint2 g_scp[(size_t)B_SZ*NH_C*S_LEN*1024];
__device__ uint2 g_arp[(size_t)M_TOT*384];
__device__ uint2 g_acp[(size_t)M_TOT*384];
__device__ uint2 g_wop[(size_t)384*1536];            // ro_w|co_w F2
__device__ uint2 g_outwp[(size_t)768*768];           // out_w F2
__device__ uint2 g_catp[(size_t)M_TOT*768];          // concat packed F1

// -------- bf16 split helpers --------------------------------------------------
__device__ __forceinline__ uint32_t bf2w(float a, float b) {
    __nv_bfloat162 t;
    t.x = __float2bfloat16(a); t.y = __float2bfloat16(b);
    return *reinterpret_cast<uint32_t*>(&t);
}
__device__ __forceinline__ uint2 packpair(float e, float o) {
    __nv_bfloat16 he = __float2bfloat16(e);
    __nv_bfloat16 ho = __float2bfloat16(o);
    float le = e - __bfloat162float(he);
    float lo = o - __bfloat162float(ho);
    uint2 r;
    __nv_bfloat162 th; th.x = he; th.y = ho;
    r.x = *reinterpret_cast<uint32_t*>(&th);
    r.y = bf2w(le, lo);
    return r;
}

__device__ __forceinline__ void mma_bf16(float* c, const uint32_t* a, const uint32_t* b) {
    asm volatile(
        "mma.sync.aligned.m16n8k16.row.col.f32.bf16.bf16.f32 "
        "{%0,%1,%2,%3}, {%4,%5,%6,%7}, {%8,%9}, {%0,%1,%2,%3};"
        : "+f"(c[0]), "+f"(c[1]), "+f"(c[2]), "+f"(c[3])
        : "r"(a[0]), "r"(a[1]), "r"(a[2]), "r"(a[3]), "r"(b[0]), "r"(b[1]));
}

// ============================================================================
// small packing kernels
// ============================================================================
__global__ void pack_f2(const float* __restrict__ src, uint2* __restrict__ dst,
                        int Nsrc, int dstN, int col_off, int total)
{
    int idx = blockIdx.x * 256 + threadIdx.x;
    if (idx >= total) return;
    int p = idx / Nsrc, n = idx % Nsrc;
    dst[(long long)p * dstN + col_off + n] =
        packpair(src[(long long)(2 * p) * Nsrc + n], src[(long long)(2 * p + 1) * Nsrc + n]);
}

__global__ void fold_bias(const float* b0, const float* b1, const float* b2,
                          const float* b3, const float* b4, const float* b5,
                          const float* rcb, const float* ccb, float* Bv)
{
    int idx = blockIdx.x * 256 + threadIdx.x;
    if (idx >= NQKV) return;
    int blk = idx / E_DIM, c = idx % E_DIM;
    const float* bs;
    switch (blk) {
        case 0: bs = b0; break; case 1: bs = b1; break; case 2: bs = b2; break;
        case 3: bs = b3; break; case 4: bs = b4; break; default: bs = b5; break;
    }
    float v = bs[c];
    if (blk == 0) v += rcb[c];
    if (blk == 3) v += ccb[c];
    Bv[idx] = v;
}

__global__ void split_f1(const float* __restrict__ src, uint2* __restrict__ dst, int totalPairs)
{
    int idx = blockIdx.x * 256 + threadIdx.x;
    if (idx >= totalPairs) return;
    float2 f = ((const float2*)src)[idx];
    dst[idx] = packpair(f.x, f.y);
}

__global__ void split_v(const float* __restrict__ qkv, uint2* __restrict__ v)
{
    int idx = blockIdx.x * 256 + threadIdx.x;
    const int total = B_SZ * 1024 * 1536;
    if (idx >= total) return;
    int b = idx / (1024 * 1536);
    int r = idx % (1024 * 1536);
    int p = r / 1536, n = r % 1536;
    int col = (n < 768) ? (1536 + n) : (3072 + n);
    long long row = (long long)(b * 2048 + 2 * p) * NQKV;
    v[idx] = packpair(qkv[row + col], qkv[row + NQKV + col]);
}

// ============================================================================
// NN GEMM, bf16x3. A: F1-packed [M x K/2], B: F2-packed [K/2 x ldbN].
// CTA 128x64, 4 warps (2m x 2n), warp tile 64x32, BK=32.
// ============================================================================
__global__ void __launch_bounds__(128) gemm_bf3_nn(
    const uint2* __restrict__ A, const uint2* __restrict__ B,
    float* __restrict__ Cf, uint2* __restrict__ Cp,
    const float* __restrict__ bias,
    int K, int lda2, int ldbN, int ldc, int ldc2,
    long long sA2, long long sBb, long long sBh,
    long long sCpb, long long sCph, int nh)
{
    __shared__ uint2 As[128 * SP_A];
    __shared__ uint2 Bs[16 * SP_BN];
    const int tid = threadIdx.x;
    const int wid = tid >> 5, lane = tid & 31;
    const int gid = lane >> 2, tig = lane & 3;
    const int wm = wid >> 1, wn = wid & 1;
    const int z = blockIdx.z, b = z / nh, h = z % nh;
    const uint2* Ap = A + (long long)z * sA2;
    const uint2* Bp = B + (long long)b * sBb + (long long)h * sBh;
    const int row0 = blockIdx.y * 128, col0 = blockIdx.x * 64;

    uint4 pa[8], pbuf[4];
    #pragma unroll
    for (int it = 0; it < 8; it++) {
        int lin = it * 128 + tid; int m = lin >> 3, p4 = (lin & 7) << 1;
        pa[it] = *(const uint4*)(Ap + (long long)(row0 + m) * lda2 + p4);
    }
    #pragma unroll
    for (int it = 0; it < 4; it++) {
        int lin = it * 128 + tid; int p = lin >> 5, n2 = (lin & 31) << 1;
        pbuf[it] = *(const uint4*)(Bp + (long long)p * ldbN + col0 + n2);
    }

    float acc[4][4][4] = {};

    for (int k0 = 0; k0 < K; k0 += 32) {
        #pragma unroll
        for (int it = 0; it < 8; it++) {
            int lin = it * 128 + tid; int m = lin >> 3, p4 = (lin & 7) << 1;
            *(uint4*)&As[m * SP_A + p4] = pa[it];
        }
        #pragma unroll
        for (int it = 0; it < 4; it++) {
            int lin = it * 128 + tid; int p = lin >> 5, n2 = (lin & 31) << 1;
            *(uint4*)&Bs[p * SP_BN + n2] = pbuf[it];
        }
        __syncthreads();
        if (k0 + 32 < K) {
            int k02 = (k0 + 32) >> 1;
            #pragma unroll
            for (int it = 0; it < 8; it++) {
                int lin = it * 128 + tid; int m = lin >> 3, p4 = (lin & 7) << 1;
                pa[it] = *(const uint4*)(Ap + (long long)(row0 + m) * lda2 + k02 + p4);
            }
            #pragma unroll
            for (int it = 0; it < 4; it++) {
                int lin = it * 128 + tid; int p = lin >> 5, n2 = (lin & 31) << 1;
                pbuf[it] = *(const uint4*)(Bp + (long long)(k02 + p) * ldbN + col0 + n2);
            }
        }
        #pragma unroll
        for (int pb2 = 0; pb2 < 16; pb2 += 8) {
            uint32_t bh[4][2], bl[4][2];
            #pragma unroll
            for (int j = 0; j < 4; j++) {
                int n = wn * 32 + j * 8 + gid;
                uint2 e0 = Bs[(pb2 + tig) * SP_BN + n];
                uint2 e1 = Bs[(pb2 + tig + 4) * SP_BN + n];
                bh[j][0] = e0.x; bl[j][0] = e0.y;
                bh[j][1] = e1.x; bl[j][1] = e1.y;
            }
            #pragma unroll
            for (int i = 0; i < 4; i++) {
                int mb = wm * 64 + i * 16 + gid;
                uint2 a0 = As[mb * SP_A + pb2 + tig];
                uint2 a1 = As[(mb + 8) * SP_A + pb2 + tig];
                uint2 a2 = As[mb * SP_A + pb2 + tig + 4];
                uint2 a3 = As[(mb + 8) * SP_A + pb2 + tig + 4];
                uint32_t ah[4] = {a0.x, a1.x, a2.x, a3.x};
                uint32_t al[4] = {a0.y, a1.y, a2.y, a3.y};
                #pragma unroll
                for (int j = 0; j < 4; j++) {
                    mma_bf16(acc[i][j], ah, bh[j]);
                    mma_bf16(acc[i][j], al, bh[j]);
                    mma_bf16(acc[i][j], ah, bl[j]);
                }
            }
        }
        __syncthreads();
    }

    uint2* Cpb = Cp ? (Cp + (long long)b * sCpb + (long long)h * sCph) : nullptr;
    #pragma unroll
    for (int i = 0; i < 4; i++) {
        int r0 = row0 + wm * 64 + i * 16 + gid;
        #pragma unroll
        for (int j = 0; j < 4; j++) {
            int c = col0 + wn * 32 + j * 8 + tig * 2;
            float b0 = 0.f, b1 = 0.f;
            if (bias) { b0 = bias[c]; b1 = bias[c + 1]; }
            float v00 = acc[i][j][0] + b0, v01 = acc[i][j][1] + b1;
            float v10 = acc[i][j][2] + b0, v11 = acc[i][j][3] + b1;
            if (Cf) {
                float2 t0 = {v00, v01}, t1 = {v10, v11};
                *(float2*)(Cf + (long long)r0 * ldc + c) = t0;
                *(float2*)(Cf + (long long)(r0 + 8) * ldc + c) = t1;
            }
            if (Cpb) {
                Cpb[(long long)r0 * ldc2 + (c >> 1)] = packpair(v00, v01);
                Cpb[(long long)(r0 + 8) * ldc2 + (c >> 1)] = packpair(v10, v11);
            }
        }
    }
}

// ============================================================================
// NT scores GEMM, bf16x3. Q,K both F1-packed. Sc = scale*Q@K^T + masks (fp32).
// ============================================================================
__global__ void __launch_bounds__(128) gemm_bf3_nt_scores(
    const uint2* __restrict__ Qb, const uint2* __restrict__ Kb,
    float* __restrict__ Sc,
    const float* __restrict__ am, const float* __restrict__ cm,
    float scale, int hd, int nh, int lda2)
{
    __shared__ uint2 As[128 * SP_A];
    __shared__ uint2 Bs[64 * SP_BT];
    const int tid = threadIdx.x;
    const int wid = tid >> 5, lane = tid & 31;
    const int gid = lane >> 2, tig = lane & 3;
    const int wm = wid >> 1, wn = wid & 1;
    const int z = blockIdx.z, b = z / nh, h = z % nh;
    const int hp = hd >> 1;
    const uint2* Qp = Qb + (long long)b * S_LEN * lda2 + h * hp;
    const uint2* Kp = Kb + (long long)b * S_LEN * lda2 + h * hp;
    float* Cpt = Sc + (long long)z * S_LEN * S_LEN;
    const int row0 = blockIdx.y * 128, col0 = blockIdx.x * 64;

    uint4 pa[8], pbuf[4];
    #pragma unroll
    for (int it = 0; it < 8; it++) {
        int lin = it * 128 + tid; int m = lin >> 3, p4 = (lin & 7) << 1;
        pa[it] = *(const uint4*)(Qp + (long long)(row0 + m) * lda2 + p4);
    }
    #pragma unroll
    for (int it = 0; it < 4; it++) {
        int lin = it * 128 + tid; int n = lin >> 3, p4 = (lin & 7) << 1;
        pbuf[it] = *(const uint4*)(Kp + (long long)(col0 + n) * lda2 + p4);
    }

    float acc[4][4][4] = {};

    for (int k0 = 0; k0 < hd; k0 += 32) {
        #pragma unroll
        for (int it = 0; it < 8; it++) {
            int lin = it * 128 + tid; int m = lin >> 3, p4 = (lin & 7) << 1;
            *(uint4*)&As[m * SP_A + p4] = pa[it];
        }
        #pragma unroll
        for (int it = 0; it < 4; it++) {
            int lin = it * 128 + tid; int n = lin >> 3, p4 = (lin & 7) << 1;
            *(uint4*)&Bs[n * SP_BT + p4] = pbuf[it];
        }
        __syncthreads();
        if (k0 + 32 < hd) {
            int k02 = (k0 + 32) >> 1;
            #pragma unroll
            for (int it = 0; it < 8; it++) {
                int lin = it * 128 + tid; int m = lin >> 3, p4 = (lin & 7) << 1;
                pa[it] = *(const uint4*)(Qp + (long long)(row0 + m) * lda2 + k02 + p4);
            }
            #pragma unroll
            for (int it = 0; it < 4; it++) {
                int lin = it * 128 + tid; int n = lin >> 3, p4 = (lin & 7) << 1;
                pbuf[it] = *(const uint4*)(Kp + (long long)(col0 + n) * lda2 + k02 + p4);
            }
        }
        #pragma unroll
        for (int pb2 = 0; pb2 < 16; pb2 += 8) {
            uint32_t bh[4][2], bl[4][2];
            #pragma unroll
            for (int j = 0; j < 4; j++) {
                int n = wn * 32 + j * 8 + gid;
                uint2 e0 = Bs[n * SP_BT + pb2 + tig];
                uint2 e1 = Bs[n * SP_BT + pb2 + tig + 4];
                bh[j][0] = e0.x; bl[j][0] = e0.y;
                bh[j][1] = e1.x; bl[j][1] = e1.y;
            }
            #pragma unroll
            for (int i = 0; i < 4; i++) {
                int mb = wm * 64 + i * 16 + gid;
                uint2 a0 = As[mb * SP_A + pb2 + tig];
                uint2 a1 = As[(mb + 8) * SP_A + pb2 + tig];
                uint2 a2 = As[mb * SP_A + pb2 + tig + 4];
                uint2 a3 = As[(mb + 8) * SP_A + pb2 + tig + 4];
                uint32_t ah[4] = {a0.x, a1.x, a2.x, a3.x};
                uint32_t al[4] = {a0.y, a1.y, a2.y, a3.y};
                #pragma unroll
                for (int j = 0; j < 4; j++) {
                    mma_bf16(acc[i][j], ah, bh[j]);
                    mma_bf16(acc[i][j], al, bh[j]);
                    mma_bf16(acc[i][j], ah, bl[j]);
                }
            }
        }
        __syncthreads();
    }

    #pragma unroll
    for (int i = 0; i < 4; i++) {
        int t0 = row0 + wm * 64 + i * 16 + gid;
        #pragma unroll
        for (int j = 0; j < 4; j++) {
            int s = col0 + wn * 32 + j * 8 + tig * 2;
            float m0 = am[b * S_LEN + s], m1 = am[b * S_LEN + s + 1];
            float n0 = m0, n1 = m1;
            if (cm) {
                const float* cmr0 = cm + ((long long)b * S_LEN + t0) * S_LEN;
                const float* cmr1 = cmr0 + 8LL * S_LEN;
                m0 += cmr0[s]; m1 += cmr0[s + 1];
                n0 += cmr1[s]; n1 += cmr1[s + 1];
            }
            float2 v0 = { acc[i][j][0] * scale + m0, acc[i][j][1] * scale + m1 };
            float2 v1 = { acc[i][j][2] * scale + n0, acc[i][j][3] * scale + n1 };
            *(float2*)(Cpt + (long long)t0 * S_LEN + s) = v0;
            *(float2*)(Cpt + (long long)(t0 + 8) * S_LEN + s) = v1;
        }
    }
}

// ============================================================================
// row softmax over 2048 + pack to F1 (bf16 hi/lo pairs)
// ============================================================================
__global__ void __launch_bounds__(256) softmax_pack(const float* __restrict__ in,
                                                    uint2* __restrict__ out)
{
    const long long row = blockIdx.x;
    const float2* r = (const float2*)(in + row * S_LEN);
    uint2* o = out + row * (S_LEN / 2);
    const int tid = threadIdx.x;
    __shared__ float red[256];

    float2 v[4];
    float mx = -1e30f;
    #pragma unroll
    for (int i = 0; i < 4; i++) {
        v[i] = r[tid + i * 256];
        mx = fmaxf(mx, fmaxf(v[i].x, v[i].y));
    }
    red[tid] = mx; __syncthreads();
    for (int s = 128; s > 0; s >>= 1) {
        if (tid < s) red[tid] = fmaxf(red[tid], red[tid + s]);
        __syncthreads();
    }
    mx = red[0];
    __syncthreads();

    float sum = 0.f;
    #pragma unroll
    for (int i = 0; i < 4; i++) {
        v[i].x = __expf(v[i].x - mx);
        v[i].y = __expf(v[i].y - mx);
        sum += v[i].x + v[i].y;
    }
    red[tid] = sum; __syncthreads();
    for (int s = 128; s > 0; s >>= 1) {
        if (tid < s) red[tid] += red[tid + s];
        __syncthreads();
    }
    const float inv = 1.0f / red[0];
    #pragma unroll
    for (int i = 0; i < 4; i++)
        o[tid + i * 256] = packpair(v[i].x * inv, v[i].y * inv);
}

// ============================================================================
template <typename T>
static T* symaddr(const void* s) {
    void* p = nullptr;
    cudaGetSymbolAddress(&p, s);
    return (T*)p;
}

extern "C" void kernel_launch(void* const* d_in, const int* in_sizes, int n_in,
                              void* d_out, int out_size)
{
    const float* x    = (const float*)d_in[0];
    const float* cm   = (const float*)d_in[1];
    const float* am   = (const float*)d_in[2];
    const float* rq_w = (const float*)d_in[3];
    const float* rk_w = (const float*)d_in[4];
    const float* rv_w = (const float*)d_in[5];
    const float* ro_w = (const float*)d_in[6];
    const float* cq_w = (const float*)d_in[7];
    const float* ck_w = (const float*)d_in[8];
    const float* cv_w = (const float*)d_in[9];
    const float* co_w = (const float*)d_in[10];
    const float* rq_b = (const float*)d_in[11];
    const float* rk_b = (const float*)d_in[12];
    const float* rv_b = (const float*)d_in[13];
    const float* ro_b = (const float*)d_in[14];
    const float* cq_b = (const float*)d_in[15];
    const float* ck_b = (const float*)d_in[16];
    const float* cv_b = (const float*)d_in[17];
    const float* co_b = (const float*)d_in[18];
    const float* r_cb = (const float*)d_in[19];
    const float* c_cb = (const float*)d_in[20];
    const float* out_w = (const float*)d_in[21];
    const float* out_b = (const float*)d_in[22];
    float* out = (float*)d_out;

    uint2* xp    = symaddr<uint2>(g_xp);
    uint2* wqkvp = symaddr<uint2>(g_wqkvp);
    float* bqkv  = symaddr<float>(g_bqkv);
    float* qkv   = symaddr<float>(g_qkv);
    uint2* qkvp  = symaddr<uint2>(g_qkvp);
    uint2* vf2   = symaddr<uint2>(g_vf2);
    float* sr    = symaddr<float>(g_sr);
    float* sc    = symaddr<float>(g_sc);
    uint2* srp   = symaddr<uint2>(g_srp);
    uint2* scp   = symaddr<uint2>(g_scp);
    uint2* arp   = symaddr<uint2>(g_arp);
    uint2* acp   = symaddr<uint2>(g_acp);
    uint2* wop   = symaddr<uint2>(g_wop);
    uint2* outwp = symaddr<uint2>(g_outwp);
    uint2* catp  = symaddr<uint2>(g_catp);

    dim3 blk(128);

    // ---- pack weights (F2) + biases ----
    {
        const int tot66 = 384 * 768;
        const float* ws[6] = {rq_w, rk_w, rv_w, cq_w, ck_w, cv_w};
        for (int i = 0; i < 6; i++)
            pack_f2<<<(tot66 + 255) / 256, 256>>>(ws[i], wqkvp, 768, NQKV, i * 768, tot66);
        pack_f2<<<(tot66 + 255) / 256, 256>>>(ro_w, wop, 768, 1536, 0, tot66);
        pack_f2<<<(tot66 + 255) / 256, 256>>>(co_w, wop, 768, 1536, 768, tot66);
        const int toto = 768 * 768;
        pack_f2<<<(toto + 255) / 256, 256>>>(out_w, outwp, 768, 768, 0, toto);
        fold_bias<<<(NQKV + 255) / 256, 256>>>(rq_b, rk_b, rv_b, cq_b, ck_b, cv_b,
                                               r_cb, c_cb, bqkv);
    }

    // ---- split x -> F1 ----
    {
        const int tp = M_TOT * 384;
        split_f1<<<(tp + 255) / 256, 256>>>(x, xp, tp);
    }

    // ---- fused QKV projection ----
    dim3 gq(NQKV / 64, M_TOT / 128, 1);
    gemm_bf3_nn<<<gq, blk>>>(xp, wqkvp, qkv, qkvp, bqkv,
                             E_DIM, 384, NQKV, NQKV, 2304,
                             0, 0, 0, 0, 0, 1);

    // ---- split V -> F2 ----
    {
        const int tv = B_SZ * 1024 * 1536;
        split_v<<<(tv + 255) / 256, 256>>>(qkv, vf2);
    }

    // ---- scores ----
    const float scale_r = 1.0f / sqrtf((float)HD_R);
    const float scale_c = 1.0f / sqrtf((float)HD_C);
    dim3 gsr(S_LEN / 64, S_LEN / 128, B_SZ * NH_R);
    gemm_bf3_nt_scores<<<gsr, blk>>>(qkvp + 0, qkvp + 384, sr,
                                     am, nullptr, scale_r, HD_R, NH_R, 2304);
    dim3 gsc(S_LEN / 64, S_LEN / 128, B_SZ * NH_C);
    gemm_bf3_nt_scores<<<gsc, blk>>>(qkvp + 1152, qkvp + 1536, sc,
                                     am, cm, scale_c, HD_C, NH_C, 2304);

    // ---- softmax + pack ----
    softmax_pack<<<B_SZ * NH_R * S_LEN, 256>>>(sr, srp);
    softmax_pack<<<B_SZ * NH_C * S_LEN, 256>>>(sc, scp);

    // ---- attn = probs @ V (packed outputs) ----
    dim3 gar(HD_R / 64, S_LEN / 128, B_SZ * NH_R);
    gemm_bf3_nn<<<gar, blk>>>(srp, vf2, nullptr, arp, nullptr,
                              S_LEN, 1024, 1536, 0, 384,
                              (long long)S_LEN * 1024,
                              (long long)1024 * 1536, HD_R,
                              (long long)S_LEN * 384, HD_R / 2, NH_R);
    dim3 gac(HD_C / 64, S_LEN / 128, B_SZ * NH_C);
    gemm_bf3_nn<<<gac, blk>>>(scp, vf2 + 768, nullptr, acp, nullptr,
                              S_LEN, 1024, 1536, 0, 384,
                              (long long)S_LEN * 1024,
                              (long long)1024 * 1536, HD_C,
                              (long long)S_LEN * 384, HD_C / 2, NH_C);

    // ---- output projections -> packed concat ----
    dim3 gp(E_DIM / 64, M_TOT / 128, 1);
    gemm_bf3_nn<<<gp, blk>>>(arp, wop, nullptr, catp, ro_b,
                             E_DIM, 384, 1536, 0, 768,
                             0, 0, 0, 0, 0, 1);
    gemm_bf3_nn<<<gp, blk>>>(acp, wop + 768, nullptr, catp + 384, co_b,
                             E_DIM, 384, 1536, 0, 768,
                             0, 0, 0, 0, 0, 1);

    // ---- final: [M,2E] @ [2E,E] + out_b -> fp32 out ----
    gemm_bf3_nn<<<gp, blk>>>(catp, outwp, out, nullptr, out_b,
                             2 * E_DIM, 768, 768, 768, 0,
                             0, 0, 0, 0, 0, 1);
}

// round 6
// speedup vs baseline: 3.1365x; 1.0335x over previous
#include <cuda_runtime.h>
#include <cuda_bf16.h>
#include <math.h>
#include <stdint.h>

#define S_LEN 2048
#define E_DIM 768
#define B_SZ  2
#define NH_R  6
#define NH_C  2
#define HD_R  128
#define HD_C  384
#define M_TOT 4096
#define NQKV  4608

// smem strides (uint2 units); stride mod 16 == 4 -> conflict-free LDS.64 frags
#define SP_A  20
#define SP_BN 68
#define SP_BT 20

// flash smem geometry (uint2 units)
#define FQ_S 68    // Q row stride (64 pairs + 4)
#define FK_S 68    // K row stride
#define FV_S 132   // V p-row stride (128 cols + 4)
#define FQ_SZ (128*FQ_S)
#define FK_SZ (64*FK_S)
#define FV_SZ (32*FV_S)
#define FLASH_SMEM ((FQ_SZ + 2*FK_SZ + 2*FV_SZ)*8 + 2*64*4)   // 207,360 B

// -------- scratch ------------------------------------------------------------
__device__ uint2 g_xp[(size_t)M_TOT*384];            // x packed F1
__device__ uint2 g_wqkvp[(size_t)384*NQKV];          // qkv weights F2
__device__ float g_bqkv[NQKV];
__device__ float g_qkv[(size_t)M_TOT*NQKV];          // fp32 qkv (for V split)
__device__ uint2 g_qkvp[(size_t)M_TOT*2304];         // qkv packed F1
__device__ uint2 g_vf2[(size_t)B_SZ*1024*1536];      // V packed F2
__device__ float g_sc[(size_t)B_SZ*NH_C*S_LEN*S_LEN];
__device__ uint2 g_scp[(size_t)B_SZ*NH_C*S_LEN*1024];
__device__ uint2 g_arp[(size_t)M_TOT*384];
__device__ uint2 g_acp[(size_t)M_TOT*384];
__device__ uint2 g_wop[(size_t)384*1536];            // ro_w|co_w F2
__device__ uint2 g_outwp[(size_t)768*768];           // out_w F2
__device__ uint2 g_catp[(size_t)M_TOT*768];          // concat packed F1

// -------- helpers --------------------------------------------------------------
__device__ __forceinline__ uint32_t smem_u32(const void* p) {
    return (uint32_t)__cvta_generic_to_shared(p);
}
#define CP16(sa, ga) asm volatile("cp.async.cg.shared.global [%0], [%1], 16;" :: "r"(sa), "l"(ga))
#define CP_COMMIT()  asm volatile("cp.async.commit_group;" ::: "memory")
#define CP_WAIT0()   asm volatile("cp.async.wait_group 0;" ::: "memory")

__device__ __forceinline__ uint32_t bf2w(float a, float b) {
    __nv_bfloat162 t;
    t.x = __float2bfloat16(a); t.y = __float2bfloat16(b);
    return *reinterpret_cast<uint32_t*>(&t);
}
__device__ __forceinline__ uint2 packpair(float e, float o) {
    __nv_bfloat16 he = __float2bfloat16(e);
    __nv_bfloat16 ho = __float2bfloat16(o);
    float le = e - __bfloat162float(he);
    float lo = o - __bfloat162float(ho);
    uint2 r;
    __nv_bfloat162 th; th.x = he; th.y = ho;
    r.x = *reinterpret_cast<uint32_t*>(&th);
    r.y = bf2w(le, lo);
    return r;
}

__device__ __forceinline__ void mma_bf16(float* c, const uint32_t* a, const uint32_t* b) {
    asm volatile(
        "mma.sync.aligned.m16n8k16.row.col.f32.bf16.bf16.f32 "
        "{%0,%1,%2,%3}, {%4,%5,%6,%7}, {%8,%9}, {%0,%1,%2,%3};"
        : "+f"(c[0]), "+f"(c[1]), "+f"(c[2]), "+f"(c[3])
        : "r"(a[0]), "r"(a[1]), "r"(a[2]), "r"(a[3]), "r"(b[0]), "r"(b[1]));
}

// ============================================================================
// small packing kernels
// ============================================================================
__global__ void pack_f2(const float* __restrict__ src, uint2* __restrict__ dst,
                        int Nsrc, int dstN, int col_off, int total)
{
    int idx = blockIdx.x * 256 + threadIdx.x;
    if (idx >= total) return;
    int p = idx / Nsrc, n = idx % Nsrc;
    dst[(long long)p * dstN + col_off + n] =
        packpair(src[(long long)(2 * p) * Nsrc + n], src[(long long)(2 * p + 1) * Nsrc + n]);
}

__global__ void fold_bias(const float* b0, const float* b1, const float* b2,
                          const float* b3, const float* b4, const float* b5,
                          const float* rcb, const float* ccb, float* Bv)
{
    int idx = blockIdx.x * 256 + threadIdx.x;
    if (idx >= NQKV) return;
    int blk = idx / E_DIM, c = idx % E_DIM;
    const float* bs;
    switch (blk) {
        case 0: bs = b0; break; case 1: bs = b1; break; case 2: bs = b2; break;
        case 3: bs = b3; break; case 4: bs = b4; break; default: bs = b5; break;
    }
    float v = bs[c];
    if (blk == 0) v += rcb[c];
    if (blk == 3) v += ccb[c];
    Bv[idx] = v;
}

__global__ void split_f1(const float* __restrict__ src, uint2* __restrict__ dst, int totalPairs)
{
    int idx = blockIdx.x * 256 + threadIdx.x;
    if (idx >= totalPairs) return;
    float2 f = ((const float2*)src)[idx];
    dst[idx] = packpair(f.x, f.y);
}

__global__ void split_v(const float* __restrict__ qkv, uint2* __restrict__ v)
{
    int idx = blockIdx.x * 256 + threadIdx.x;
    const int total = B_SZ * 1024 * 1536;
    if (idx >= total) return;
    int b = idx / (1024 * 1536);
    int r = idx % (1024 * 1536);
    int p = r / 1536, n = r % 1536;
    int col = (n < 768) ? (1536 + n) : (3072 + n);
    long long row = (long long)(b * 2048 + 2 * p) * NQKV;
    v[idx] = packpair(qkv[row + col], qkv[row + NQKV + col]);
}

// ============================================================================
// NN GEMM, bf16x3 (round-4, unchanged)
// ============================================================================
__global__ void __launch_bounds__(128) gemm_bf3_nn(
    const uint2* __restrict__ A, const uint2* __restrict__ B,
    float* __restrict__ Cf, uint2* __restrict__ Cp,
    const float* __restrict__ bias,
    int K, int lda2, int ldbN, int ldc, int ldc2,
    long long sA2, long long sBb, long long sBh,
    long long sCpb, long long sCph, int nh)
{
    __shared__ uint2 As[128 * SP_A];
    __shared__ uint2 Bs[16 * SP_BN];
    const int tid = threadIdx.x;
    const int wid = tid >> 5, lane = tid & 31;
    const int gid = lane >> 2, tig = lane & 3;
    const int wm = wid >> 1, wn = wid & 1;
    const int z = blockIdx.z, b = z / nh, h = z % nh;
    const uint2* Ap = A + (long long)z * sA2;
    const uint2* Bp = B + (long long)b * sBb + (long long)h * sBh;
    const int row0 = blockIdx.y * 128, col0 = blockIdx.x * 64;

    uint4 pa[8], pbuf[4];
    #pragma unroll
    for (int it = 0; it < 8; it++) {
        int lin = it * 128 + tid; int m = lin >> 3, p4 = (lin & 7) << 1;
        pa[it] = *(const uint4*)(Ap + (long long)(row0 + m) * lda2 + p4);
    }
    #pragma unroll
    for (int it = 0; it < 4; it++) {
        int lin = it * 128 + tid; int p = lin >> 5, n2 = (lin & 31) << 1;
        pbuf[it] = *(const uint4*)(Bp + (long long)p * ldbN + col0 + n2);
    }

    float acc[4][4][4] = {};

    for (int k0 = 0; k0 < K; k0 += 32) {
        #pragma unroll
        for (int it = 0; it < 8; it++) {
            int lin = it * 128 + tid; int m = lin >> 3, p4 = (lin & 7) << 1;
            *(uint4*)&As[m * SP_A + p4] = pa[it];
        }
        #pragma unroll
        for (int it = 0; it < 4; it++) {
            int lin = it * 128 + tid; int p = lin >> 5, n2 = (lin & 31) << 1;
            *(uint4*)&Bs[p * SP_BN + n2] = pbuf[it];
        }
        __syncthreads();
        if (k0 + 32 < K) {
            int k02 = (k0 + 32) >> 1;
            #pragma unroll
            for (int it = 0; it < 8; it++) {
                int lin = it * 128 + tid; int m = lin >> 3, p4 = (lin & 7) << 1;
                pa[it] = *(const uint4*)(Ap + (long long)(row0 + m) * lda2 + k02 + p4);
            }
            #pragma unroll
            for (int it = 0; it < 4; it++) {
                int lin = it * 128 + tid; int p = lin >> 5, n2 = (lin & 31) << 1;
                pbuf[it] = *(const uint4*)(Bp + (long long)(k02 + p) * ldbN + col0 + n2);
            }
        }
        #pragma unroll
        for (int pb2 = 0; pb2 < 16; pb2 += 8) {
            uint32_t bh[4][2], bl[4][2];
            #pragma unroll
            for (int j = 0; j < 4; j++) {
                int n = wn * 32 + j * 8 + gid;
                uint2 e0 = Bs[(pb2 + tig) * SP_BN + n];
                uint2 e1 = Bs[(pb2 + tig + 4) * SP_BN + n];
                bh[j][0] = e0.x; bl[j][0] = e0.y;
                bh[j][1] = e1.x; bl[j][1] = e1.y;
            }
            #pragma unroll
            for (int i = 0; i < 4; i++) {
                int mb = wm * 64 + i * 16 + gid;
                uint2 a0 = As[mb * SP_A + pb2 + tig];
                uint2 a1 = As[(mb + 8) * SP_A + pb2 + tig];
                uint2 a2 = As[mb * SP_A + pb2 + tig + 4];
                uint2 a3 = As[(mb + 8) * SP_A + pb2 + tig + 4];
                uint32_t ah[4] = {a0.x, a1.x, a2.x, a3.x};
                uint32_t al[4] = {a0.y, a1.y, a2.y, a3.y};
                #pragma unroll
                for (int j = 0; j < 4; j++) {
                    mma_bf16(acc[i][j], ah, bh[j]);
                    mma_bf16(acc[i][j], al, bh[j]);
                    mma_bf16(acc[i][j], ah, bl[j]);
                }
            }
        }
        __syncthreads();
    }

    uint2* Cpb = Cp ? (Cp + (long long)b * sCpb + (long long)h * sCph) : nullptr;
    #pragma unroll
    for (int i = 0; i < 4; i++) {
        int r0 = row0 + wm * 64 + i * 16 + gid;
        #pragma unroll
        for (int j = 0; j < 4; j++) {
            int c = col0 + wn * 32 + j * 8 + tig * 2;
            float b0 = 0.f, b1 = 0.f;
            if (bias) { b0 = bias[c]; b1 = bias[c + 1]; }
            float v00 = acc[i][j][0] + b0, v01 = acc[i][j][1] + b1;
            float v10 = acc[i][j][2] + b0, v11 = acc[i][j][3] + b1;
            if (Cf) {
                float2 t0 = {v00, v01}, t1 = {v10, v11};
                *(float2*)(Cf + (long long)r0 * ldc + c) = t0;
                *(float2*)(Cf + (long long)(r0 + 8) * ldc + c) = t1;
            }
            if (Cpb) {
                Cpb[(long long)r0 * ldc2 + (c >> 1)] = packpair(v00, v01);
                Cpb[(long long)(r0 + 8) * ldc2 + (c >> 1)] = packpair(v10, v11);
            }
        }
    }
}

// ============================================================================
// NT scores GEMM (round-4, unchanged; used by cultural branch only)
// ============================================================================
__global__ void __launch_bounds__(128) gemm_bf3_nt_scores(
    const uint2* __restrict__ Qb, const uint2* __restrict__ Kb,
    float* __restrict__ Sc,
    const float* __restrict__ am, const float* __restrict__ cm,
    float scale, int hd, int nh, int lda2)
{
    __shared__ uint2 As[128 * SP_A];
    __shared__ uint2 Bs[64 * SP_BT];
    const int tid = threadIdx.x;
    const int wid = tid >> 5, lane = tid & 31;
    const int gid = lane >> 2, tig = lane & 3;
    const int wm = wid >> 1, wn = wid & 1;
    const int z = blockIdx.z, b = z / nh, h = z % nh;
    const int hp = hd >> 1;
    const uint2* Qp = Qb + (long long)b * S_LEN * lda2 + h * hp;
    const uint2* Kp = Kb + (long long)b * S_LEN * lda2 + h * hp;
    float* Cpt = Sc + (long long)z * S_LEN * S_LEN;
    const int row0 = blockIdx.y * 128, col0 = blockIdx.x * 64;

    uint4 pa[8], pbuf[4];
    #pragma unroll
    for (int it = 0; it < 8; it++) {
        int lin = it * 128 + tid; int m = lin >> 3, p4 = (lin & 7) << 1;
        pa[it] = *(const uint4*)(Qp + (long long)(row0 + m) * lda2 + p4);
    }
    #pragma unroll
    for (int it = 0; it < 4; it++) {
        int lin = it * 128 + tid; int n = lin >> 3, p4 = (lin & 7) << 1;
        pbuf[it] = *(const uint4*)(Kp + (long long)(col0 + n) * lda2 + p4);
    }

    float acc[4][4][4] = {};

    for (int k0 = 0; k0 < hd; k0 += 32) {
        #pragma unroll
        for (int it = 0; it < 8; it++) {
            int lin = it * 128 + tid; int m = lin >> 3, p4 = (lin & 7) << 1;
            *(uint4*)&As[m * SP_A + p4] = pa[it];
        }
        #pragma unroll
        for (int it = 0; it < 4; it++) {
            int lin = it * 128 + tid; int n = lin >> 3, p4 = (lin & 7) << 1;
            *(uint4*)&Bs[n * SP_BT + p4] = pbuf[it];
        }
        __syncthreads();
        if (k0 + 32 < hd) {
            int k02 = (k0 + 32) >> 1;
            #pragma unroll
            for (int it = 0; it < 8; it++) {
                int lin = it * 128 + tid; int m = lin >> 3, p4 = (lin & 7) << 1;
                pa[it] = *(const uint4*)(Qp + (long long)(row0 + m) * lda2 + k02 + p4);
            }
            #pragma unroll
            for (int it = 0; it < 4; it++) {
                int lin = it * 128 + tid; int n = lin >> 3, p4 = (lin & 7) << 1;
                pbuf[it] = *(const uint4*)(Kp + (long long)(col0 + n) * lda2 + k02 + p4);
            }
        }
        #pragma unroll
        for (int pb2 = 0; pb2 < 16; pb2 += 8) {
            uint32_t bh[4][2], bl[4][2];
            #pragma unroll
            for (int j = 0; j < 4; j++) {
                int n = wn * 32 + j * 8 + gid;
                uint2 e0 = Bs[n * SP_BT + pb2 + tig];
                uint2 e1 = Bs[n * SP_BT + pb2 + tig + 4];
                bh[j][0] = e0.x; bl[j][0] = e0.y;
                bh[j][1] = e1.x; bl[j][1] = e1.y;
            }
            #pragma unroll
            for (int i = 0; i < 4; i++) {
                int mb = wm * 64 + i * 16 + gid;
                uint2 a0 = As[mb * SP_A + pb2 + tig];
                uint2 a1 = As[(mb + 8) * SP_A + pb2 + tig];
                uint2 a2 = As[mb * SP_A + pb2 + tig + 4];
                uint2 a3 = As[(mb + 8) * SP_A + pb2 + tig + 4];
                uint32_t ah[4] = {a0.x, a1.x, a2.x, a3.x};
                uint32_t al[4] = {a0.y, a1.y, a2.y, a3.y};
                #pragma unroll
                for (int j = 0; j < 4; j++) {
                    mma_bf16(acc[i][j], ah, bh[j]);
                    mma_bf16(acc[i][j], al, bh[j]);
                    mma_bf16(acc[i][j], ah, bl[j]);
                }
            }
        }
        __syncthreads();
    }

    #pragma unroll
    for (int i = 0; i < 4; i++) {
        int t0 = row0 + wm * 64 + i * 16 + gid;
        #pragma unroll
        for (int j = 0; j < 4; j++) {
            int s = col0 + wn * 32 + j * 8 + tig * 2;
            float m0 = am[b * S_LEN + s], m1 = am[b * S_LEN + s + 1];
            float n0 = m0, n1 = m1;
            if (cm) {
                const float* cmr0 = cm + ((long long)b * S_LEN + t0) * S_LEN;
                const float* cmr1 = cmr0 + 8LL * S_LEN;
                m0 += cmr0[s]; m1 += cmr0[s + 1];
                n0 += cmr1[s]; n1 += cmr1[s + 1];
            }
            float2 v0 = { acc[i][j][0] * scale + m0, acc[i][j][1] * scale + m1 };
            float2 v1 = { acc[i][j][2] * scale + n0, acc[i][j][3] * scale + n1 };
            *(float2*)(Cpt + (long long)t0 * S_LEN + s) = v0;
            *(float2*)(Cpt + (long long)(t0 + 8) * S_LEN + s) = v1;
        }
    }
}

// ============================================================================
// Flash-fused regular branch: scores + mask + softmax + P@V in one kernel.
// CTA 256 thr / 8 warps, Q-tile 128 (16 rows/warp), KV-tile 64, hd=128.
// Q/K from F1 qkvp; V from F2 vf2; O -> F1 arp. Double-buffered K/V cp.async.
// ============================================================================
__global__ void __launch_bounds__(256, 1) flash_reg(
    const uint2* __restrict__ qkvp, const uint2* __restrict__ vf2,
    const float* __restrict__ am, uint2* __restrict__ arp, float scale)
{
    extern __shared__ uint2 sm[];
    uint2* Qs = sm;                       // 128 x FQ_S
    uint2* Ks = Qs + FQ_SZ;               // 2 x 64 x FK_S
    uint2* Vs = Ks + 2 * FK_SZ;           // 2 x 32 x FV_S
    float* ams = (float*)(Vs + 2 * FV_SZ);// 2 x 64

    const int tid = threadIdx.x, wid = tid >> 5, lane = tid & 31;
    const int gid = lane >> 2, tig = lane & 3;
    const int qt = blockIdx.x;
    const int z = blockIdx.y, b = z / NH_R, h = z % NH_R;

    const long long qrow0 = (long long)b * S_LEN + qt * 128;
    const uint2* Qg = qkvp + qrow0 * 2304 + h * 64;
    const uint2* Kg = qkvp + (long long)b * S_LEN * 2304 + 384 + h * 64;
    const uint2* Vg = vf2 + (long long)b * 1024 * 1536 + h * 128;
    const float* amb = am + (long long)b * S_LEN;

    // ---- load Q (async) ----
    #pragma unroll
    for (int it = 0; it < 16; it++) {
        int lin = it * 256 + tid;
        int r = lin >> 5, p2 = (lin & 31) << 1;
        CP16(smem_u32(&Qs[r * FQ_S + p2]), Qg + (long long)r * 2304 + p2);
    }
    // ---- load K0/V0/am0 ----
    {
        #pragma unroll
        for (int it = 0; it < 8; it++) {
            int lin = it * 256 + tid;
            int r = lin >> 5, p2 = (lin & 31) << 1;
            CP16(smem_u32(&Ks[r * FK_S + p2]), Kg + (long long)r * 2304 + p2);
        }
        #pragma unroll
        for (int it = 0; it < 8; it++) {
            int lin = it * 256 + tid;
            int p = lin >> 6, n2 = (lin & 63) << 1;
            CP16(smem_u32(&Vs[p * FV_S + n2]), Vg + (long long)p * 1536 + n2);
        }
        if (tid < 16) CP16(smem_u32(&ams[tid * 4]), amb + tid * 4);
    }
    CP_COMMIT();

    float oac[16][4] = {};
    float m0 = -1e30f, m1 = -1e30f, l0 = 0.f, l1 = 0.f;
    const int mrow = wid * 16;

    CP_WAIT0();
    __syncthreads();

    for (int kt = 0; kt < 32; kt++) {
        // prefetch next K/V tile
        if (kt + 1 < 32) {
            int nb = (kt + 1) & 1;
            uint2* Kd = Ks + nb * FK_SZ;
            uint2* Vd = Vs + nb * FV_SZ;
            #pragma unroll
            for (int it = 0; it < 8; it++) {
                int lin = it * 256 + tid;
                int r = lin >> 5, p2 = (lin & 31) << 1;
                CP16(smem_u32(&Kd[r * FK_S + p2]),
                     Kg + (long long)((kt + 1) * 64 + r) * 2304 + p2);
            }
            #pragma unroll
            for (int it = 0; it < 8; it++) {
                int lin = it * 256 + tid;
                int p = lin >> 6, n2 = (lin & 63) << 1;
                CP16(smem_u32(&Vd[p * FV_S + n2]),
                     Vg + (long long)((kt + 1) * 32 + p) * 1536 + n2);
            }
            if (tid < 16)
                CP16(smem_u32(&ams[nb * 64 + tid * 4]), amb + (kt + 1) * 64 + tid * 4);
            CP_COMMIT();
        }

        const uint2* Kb = Ks + (kt & 1) * FK_SZ;
        const uint2* Vb = Vs + (kt & 1) * FV_SZ;
        const float* amc = ams + (kt & 1) * 64;

        // ---- S = Q @ K^T (bf16x3) ----
        float sac[8][4] = {};
        #pragma unroll
        for (int t = 0; t < 8; t++) {
            uint2 a0 = Qs[(mrow + gid) * FQ_S + 8 * t + tig];
            uint2 a1 = Qs[(mrow + gid + 8) * FQ_S + 8 * t + tig];
            uint2 a2 = Qs[(mrow + gid) * FQ_S + 8 * t + tig + 4];
            uint2 a3 = Qs[(mrow + gid + 8) * FQ_S + 8 * t + tig + 4];
            uint32_t ah[4] = {a0.x, a1.x, a2.x, a3.x};
            uint32_t al[4] = {a0.y, a1.y, a2.y, a3.y};
            #pragma unroll
            for (int j = 0; j < 8; j++) {
                uint2 e0 = Kb[(8 * j + gid) * FK_S + 8 * t + tig];
                uint2 e1 = Kb[(8 * j + gid) * FK_S + 8 * t + tig + 4];
                uint32_t bh[2] = {e0.x, e1.x};
                uint32_t bl[2] = {e0.y, e1.y};
                mma_bf16(sac[j], ah, bh);
                mma_bf16(sac[j], al, bh);
                mma_bf16(sac[j], ah, bl);
            }
        }

        // ---- scale + mask + online softmax ----
        float mx0 = -1e30f, mx1 = -1e30f;
        #pragma unroll
        for (int j = 0; j < 8; j++) {
            float a0 = amc[8 * j + 2 * tig], a1 = amc[8 * j + 2 * tig + 1];
            sac[j][0] = sac[j][0] * scale + a0;
            sac[j][1] = sac[j][1] * scale + a1;
            sac[j][2] = sac[j][2] * scale + a0;
            sac[j][3] = sac[j][3] * scale + a1;
            mx0 = fmaxf(mx0, fmaxf(sac[j][0], sac[j][1]));
            mx1 = fmaxf(mx1, fmaxf(sac[j][2], sac[j][3]));
        }
        mx0 = fmaxf(mx0, __shfl_xor_sync(0xffffffffu, mx0, 1));
        mx0 = fmaxf(mx0, __shfl_xor_sync(0xffffffffu, mx0, 2));
        mx1 = fmaxf(mx1, __shfl_xor_sync(0xffffffffu, mx1, 1));
        mx1 = fmaxf(mx1, __shfl_xor_sync(0xffffffffu, mx1, 2));
        float mn0 = fmaxf(m0, mx0), mn1 = fmaxf(m1, mx1);
        float sc0 = __expf(m0 - mn0), sc1 = __expf(m1 - mn1);
        float ps0 = 0.f, ps1 = 0.f;
        #pragma unroll
        for (int j = 0; j < 8; j++) {
            sac[j][0] = __expf(sac[j][0] - mn0);
            sac[j][1] = __expf(sac[j][1] - mn0);
            sac[j][2] = __expf(sac[j][2] - mn1);
            sac[j][3] = __expf(sac[j][3] - mn1);
            ps0 += sac[j][0] + sac[j][1];
            ps1 += sac[j][2] + sac[j][3];
        }
        ps0 += __shfl_xor_sync(0xffffffffu, ps0, 1);
        ps0 += __shfl_xor_sync(0xffffffffu, ps0, 2);
        ps1 += __shfl_xor_sync(0xffffffffu, ps1, 1);
        ps1 += __shfl_xor_sync(0xffffffffu, ps1, 2);
        l0 = l0 * sc0 + ps0;
        l1 = l1 * sc1 + ps1;
        m0 = mn0; m1 = mn1;

        // rescale O
        #pragma unroll
        for (int n = 0; n < 16; n++) {
            oac[n][0] *= sc0; oac[n][1] *= sc0;
            oac[n][2] *= sc1; oac[n][3] *= sc1;
        }

        // ---- P register A-fragments (S-frag layout == A-frag layout) ----
        uint32_t ph[4][4], pl[4][4];
        #pragma unroll
        for (int t = 0; t < 4; t++) {
            uint2 w0 = packpair(sac[2 * t][0], sac[2 * t][1]);
            uint2 w1 = packpair(sac[2 * t][2], sac[2 * t][3]);
            uint2 w2 = packpair(sac[2 * t + 1][0], sac[2 * t + 1][1]);
            uint2 w3 = packpair(sac[2 * t + 1][2], sac[2 * t + 1][3]);
            ph[t][0] = w0.x; pl[t][0] = w0.y;
            ph[t][1] = w1.x; pl[t][1] = w1.y;
            ph[t][2] = w2.x; pl[t][2] = w2.y;
            ph[t][3] = w3.x; pl[t][3] = w3.y;
        }

        // ---- O += P @ V ----
        #pragma unroll
        for (int t = 0; t < 4; t++) {
            #pragma unroll
            for (int n = 0; n < 16; n++) {
                uint2 e0 = Vb[(8 * t + tig) * FV_S + 8 * n + gid];
                uint2 e1 = Vb[(8 * t + tig + 4) * FV_S + 8 * n + gid];
                uint32_t bh[2] = {e0.x, e1.x};
                uint32_t bl[2] = {e0.y, e1.y};
                mma_bf16(oac[n], ph[t], bh);
                mma_bf16(oac[n], pl[t], bh);
                mma_bf16(oac[n], ph[t], bl);
            }
        }

        if (kt + 1 < 32) {
            CP_WAIT0();
            __syncthreads();
        }
    }

    // ---- epilogue: O/l -> arp (F1) ----
    float rl0 = 1.f / l0, rl1 = 1.f / l1;
    long long r0 = qrow0 + mrow + gid;
    uint2* op0 = arp + r0 * 384 + h * 64;
    uint2* op1 = op0 + 8LL * 384;
    #pragma unroll
    for (int n = 0; n < 16; n++) {
        op0[4 * n + tig] = packpair(oac[n][0] * rl0, oac[n][1] * rl0);
        op1[4 * n + tig] = packpair(oac[n][2] * rl1, oac[n][3] * rl1);
    }
}

// ============================================================================
// row softmax + pack to F1 (cultural branch)
// ============================================================================
__global__ void __launch_bounds__(256) softmax_pack(const float* __restrict__ in,
                                                    uint2* __restrict__ out)
{
    const long long row = blockIdx.x;
    const float2* r = (const float2*)(in + row * S_LEN);
    uint2* o = out + row * (S_LEN / 2);
    const int tid = threadIdx.x;
    __shared__ float red[256];

    float2 v[4];
    float mx = -1e30f;
    #pragma unroll
    for (int i = 0; i < 4; i++) {
        v[i] = r[tid + i * 256];
        mx = fmaxf(mx, fmaxf(v[i].x, v[i].y));
    }
    red[tid] = mx; __syncthreads();
    for (int s = 128; s > 0; s >>= 1) {
        if (tid < s) red[tid] = fmaxf(red[tid], red[tid + s]);
        __syncthreads();
    }
    mx = red[0];
    __syncthreads();

    float sum = 0.f;
    #pragma unroll
    for (int i = 0; i < 4; i++) {
        v[i].x = __expf(v[i].x - mx);
        v[i].y = __expf(v[i].y - mx);
        sum += v[i].x + v[i].y;
    }
    red[tid] = sum; __syncthreads();
    for (int s = 128; s > 0; s >>= 1) {
        if (tid < s) red[tid] += red[tid + s];
        __syncthreads();
    }
    const float inv = 1.0f / red[0];
    #pragma unroll
    for (int i = 0; i < 4; i++)
        o[tid + i * 256] = packpair(v[i].x * inv, v[i].y * inv);
}

// ============================================================================
template <typename T>
static T* symaddr(const void* s) {
    void* p = nullptr;
    cudaGetSymbolAddress(&p, s);
    return (T*)p;
}

extern "C" void kernel_launch(void* const* d_in, const int* in_sizes, int n_in,
                              void* d_out, int out_size)
{
    const float* x    = (const float*)d_in[0];
    const float* cm   = (const float*)d_in[1];
    const float* am   = (const float*)d_in[2];
    const float* rq_w = (const float*)d_in[3];
    const float* rk_w = (const float*)d_in[4];
    const float* rv_w = (const float*)d_in[5];
    const float* ro_w = (const float*)d_in[6];
    const float* cq_w = (const float*)d_in[7];
    const float* ck_w = (const float*)d_in[8];
    const float* cv_w = (const float*)d_in[9];
    const float* co_w = (const float*)d_in[10];
    const float* rq_b = (const float*)d_in[11];
    const float* rk_b = (const float*)d_in[12];
    const float* rv_b = (const float*)d_in[13];
    const float* ro_b = (const float*)d_in[14];
    const float* cq_b = (const float*)d_in[15];
    const float* ck_b = (const float*)d_in[16];
    const float* cv_b = (const float*)d_in[17];
    const float* co_b = (const float*)d_in[18];
    const float* r_cb = (const float*)d_in[19];
    const float* c_cb = (const float*)d_in[20];
    const float* out_w = (const float*)d_in[21];
    const float* out_b = (const float*)d_in[22];
    float* out = (float*)d_out;

    uint2* xp    = symaddr<uint2>(g_xp);
    uint2* wqkvp = symaddr<uint2>(g_wqkvp);
    float* bqkv  = symaddr<float>(g_bqkv);
    float* qkv   = symaddr<float>(g_qkv);
    uint2* qkvp  = symaddr<uint2>(g_qkvp);
    uint2* vf2   = symaddr<uint2>(g_vf2);
    float* sc    = symaddr<float>(g_sc);
    uint2* scp   = symaddr<uint2>(g_scp);
    uint2* arp   = symaddr<uint2>(g_arp);
    uint2* acp   = symaddr<uint2>(g_acp);
    uint2* wop   = symaddr<uint2>(g_wop);
    uint2* outwp = symaddr<uint2>(g_outwp);
    uint2* catp  = symaddr<uint2>(g_catp);

    cudaFuncSetAttribute(flash_reg, cudaFuncAttributeMaxDynamicSharedMemorySize, FLASH_SMEM);

    dim3 blk(128);

    // ---- pack weights (F2) + biases ----
    {
        const int tot66 = 384 * 768;
        const float* ws[6] = {rq_w, rk_w, rv_w, cq_w, ck_w, cv_w};
        for (int i = 0; i < 6; i++)
            pack_f2<<<(tot66 + 255) / 256, 256>>>(ws[i], wqkvp, 768, NQKV, i * 768, tot66);
        pack_f2<<<(tot66 + 255) / 256, 256>>>(ro_w, wop, 768, 1536, 0, tot66);
        pack_f2<<<(tot66 + 255) / 256, 256>>>(co_w, wop, 768, 1536, 768, tot66);
        const int toto = 768 * 768;
        pack_f2<<<(toto + 255) / 256, 256>>>(out_w, outwp, 768, 768, 0, toto);
        fold_bias<<<(NQKV + 255) / 256, 256>>>(rq_b, rk_b, rv_b, cq_b, ck_b, cv_b,
                                               r_cb, c_cb, bqkv);
    }

    // ---- split x -> F1 ----
    {
        const int tp = M_TOT * 384;
        split_f1<<<(tp + 255) / 256, 256>>>(x, xp, tp);
    }

    // ---- fused QKV projection ----
    dim3 gq(NQKV / 64, M_TOT / 128, 1);
    gemm_bf3_nn<<<gq, blk>>>(xp, wqkvp, qkv, qkvp, bqkv,
                             E_DIM, 384, NQKV, NQKV, 2304,
                             0, 0, 0, 0, 0, 1);

    // ---- split V -> F2 ----
    {
        const int tv = B_SZ * 1024 * 1536;
        split_v<<<(tv + 255) / 256, 256>>>(qkv, vf2);
    }

    // ---- regular branch: flash-fused attention ----
    {
        const float scale_r = 1.0f / sqrtf((float)HD_R);
        dim3 gf(16, B_SZ * NH_R);
        flash_reg<<<gf, 256, FLASH_SMEM>>>(qkvp, vf2, am, arp, scale_r);
    }

    // ---- cultural branch: two-pass ----
    const float scale_c = 1.0f / sqrtf((float)HD_C);
    dim3 gsc(S_LEN / 64, S_LEN / 128, B_SZ * NH_C);
    gemm_bf3_nt_scores<<<gsc, blk>>>(qkvp + 1152, qkvp + 1536, sc,
                                     am, cm, scale_c, HD_C, NH_C, 2304);
    softmax_pack<<<B_SZ * NH_C * S_LEN, 256>>>(sc, scp);
    dim3 gac(HD_C / 64, S_LEN / 128, B_SZ * NH_C);
    gemm_bf3_nn<<<gac, blk>>>(scp, vf2 + 768, nullptr, acp, nullptr,
                              S_LEN, 1024, 1536, 0, 384,
                              (long long)S_LEN * 1024,
                              (long long)1024 * 1536, HD_C,
                              (long long)S_LEN * 384, HD_C / 2, NH_C);

    // ---- output projections -> packed concat ----
    dim3 gp(E_DIM / 64, M_TOT / 128, 1);
    gemm_bf3_nn<<<gp, blk>>>(arp, wop, nullptr, catp, ro_b,
                             E_DIM, 384, 1536, 0, 768,
                             0, 0, 0, 0, 0, 1);
    gemm_bf3_nn<<<gp, blk>>>(acp, wop + 768, nullptr, catp + 384, co_b,
                             E_DIM, 384, 1536, 0, 768,
                             0, 0, 0, 0, 0, 1);

    // ---- final: [M,2E] @ [2E,E] + out_b -> fp32 out ----
    gemm_bf3_nn<<<gp, blk>>>(catp, outwp, out, nullptr, out_b,
                             2 * E_DIM, 768, 768, 768, 0,
                             0, 0, 0, 0, 0, 1);
}